// round 1
// baseline (speedup 1.0000x reference)
#include <cuda_runtime.h>

// ---------------------------------------------------------------------------
// Focus-DETR encoder (FCGTransformerEncoder) — fp32 baseline
// L=6, B=4, N=23890, K=1024, D=256, H=8, hd=32, FFN=1024, NCLS=15
// ---------------------------------------------------------------------------

#define L_LAYERS 6
#define Bn 4
#define NN 23890
#define Kn 1024
#define Dn 256
#define Hn 8
#define HDn 32
#define FFNn 1024
#define NCLSn 15

#define ROWS (Bn * Kn)          // 4096
#define RD   (ROWS * Dn)        // 1048576 floats per [B*K, D] buffer

// Scratch: tgt, qk, Q, K, V, att, x, y (each RD) + h (ROWS*FFN)
__device__ float g_scratch[8 * RD + ROWS * FFNn];

#define OFF_TGT 0
#define OFF_QK  (1 * RD)
#define OFF_Q   (2 * RD)
#define OFF_K   (3 * RD)
#define OFF_V   (4 * RD)
#define OFF_ATT (5 * RD)
#define OFF_X   (6 * RD)
#define OFF_Y   (7 * RD)
#define OFF_H   (8 * RD)

// ---------------------------------------------------------------------------
// Gather + MCSP score modulation:
//   idx = inds[l][b][j]; q = output[b, idx]; qp = query_pos[b, idx]
//   score = q @ W_cls + b_cls  (15 classes);  mc = sigmoid(max score) * fg
//   tgt = q * mc;  qk = tgt + qp
// One block (256 threads) per row; thread t owns channel t.
// ---------------------------------------------------------------------------
__global__ __launch_bounds__(256) void gather_cls_kernel(
    const float* __restrict__ out, const float* __restrict__ qpos,
    const float* __restrict__ fgs, const int* __restrict__ il,
    const float* __restrict__ Wcls, const float* __restrict__ bcls,
    float* __restrict__ tgt, float* __restrict__ qk)
{
    int row = blockIdx.x;          // 0..ROWS-1
    int b   = row >> 10;           // row / K
    int t   = threadIdx.x;         // channel
    int idx = il[row];
    size_t src = ((size_t)b * NN + idx) * Dn + t;
    float qv = out[src];

    // per-thread partial class scores
    float part[NCLSn];
#pragma unroll
    for (int c = 0; c < NCLSn; c++) part[c] = qv * Wcls[t * NCLSn + c];

    __shared__ float red[8][NCLSn];
#pragma unroll
    for (int c = 0; c < NCLSn; c++) {
        float v = part[c];
#pragma unroll
        for (int o = 16; o; o >>= 1) v += __shfl_down_sync(0xffffffffu, v, o);
        if ((t & 31) == 0) red[t >> 5][c] = v;
    }
    __syncthreads();

    __shared__ float s_mc;
    if (t == 0) {
        float mx = -1e30f;
#pragma unroll
        for (int c = 0; c < NCLSn; c++) {
            float sum = bcls[c];
#pragma unroll
            for (int w = 0; w < 8; w++) sum += red[w][c];
            mx = fmaxf(mx, sum);
        }
        float sig = 1.0f / (1.0f + __expf(-mx));   // max(sigmoid) == sigmoid(max)
        s_mc = sig * fgs[(size_t)b * NN + idx];
    }
    __syncthreads();

    float tv = qv * s_mc;
    tgt[(size_t)row * Dn + t] = tv;
    qk[(size_t)row * Dn + t]  = tv + qpos[src];
}

// ---------------------------------------------------------------------------
// SGEMM: C[M, Ncols] = A[M, Kd] @ W[Kd, Ncols] + bias (+ optional ReLU)
// 64x64 tile, BK=16, 256 threads, 4x4 micro-tile per thread.
// M % 64 == 0, Ncols % 64 == 0, Kd % 16 == 0 (always true here).
// ---------------------------------------------------------------------------
__global__ __launch_bounds__(256) void sgemm64(
    const float* __restrict__ A, const float* __restrict__ W,
    const float* __restrict__ bias, float* __restrict__ C,
    int M, int Ncols, int Kd, int relu)
{
    __shared__ __align__(16) float As[16][68];   // [k][m], padded
    __shared__ __align__(16) float Ws[16][64];   // [k][n]

    int tid = threadIdx.x;
    int tx = tid & 15, ty = tid >> 4;
    int bm = blockIdx.y << 6, bn = blockIdx.x << 6;

    float acc[4][4];
#pragma unroll
    for (int i = 0; i < 4; i++)
#pragma unroll
        for (int j = 0; j < 4; j++) acc[i][j] = 0.0f;

    int am = tid >> 2;            // 0..63 : row within A tile
    int ak = (tid & 3) << 2;      // 0,4,8,12 : k offset (float4)
    int wr = tid >> 4;            // 0..15 : k row of W tile
    int wc = (tid & 15) << 2;     // 0..60 : col offset (float4)

    const float* Ap = A + (size_t)(bm + am) * Kd + ak;
    const float* Wp = W + (size_t)wr * Ncols + bn + wc;

    for (int k0 = 0; k0 < Kd; k0 += 16) {
        float4 av = *(const float4*)(Ap + k0);
        float4 wv = *(const float4*)(Wp + (size_t)k0 * Ncols);
        As[ak + 0][am] = av.x;
        As[ak + 1][am] = av.y;
        As[ak + 2][am] = av.z;
        As[ak + 3][am] = av.w;
        *(float4*)&Ws[wr][wc] = wv;
        __syncthreads();

#pragma unroll
        for (int kk = 0; kk < 16; kk++) {
            float4 a = *(const float4*)&As[kk][ty << 2];
            float4 w = *(const float4*)&Ws[kk][tx << 2];
            acc[0][0] += a.x * w.x; acc[0][1] += a.x * w.y; acc[0][2] += a.x * w.z; acc[0][3] += a.x * w.w;
            acc[1][0] += a.y * w.x; acc[1][1] += a.y * w.y; acc[1][2] += a.y * w.z; acc[1][3] += a.y * w.w;
            acc[2][0] += a.z * w.x; acc[2][1] += a.z * w.y; acc[2][2] += a.z * w.z; acc[2][3] += a.z * w.w;
            acc[3][0] += a.w * w.x; acc[3][1] += a.w * w.y; acc[3][2] += a.w * w.z; acc[3][3] += a.w * w.w;
        }
        __syncthreads();
    }

#pragma unroll
    for (int i = 0; i < 4; i++) {
        int r = bm + (ty << 2) + i;
#pragma unroll
        for (int j = 0; j < 4; j++) {
            int c = bn + (tx << 2) + j;
            float v = acc[i][j] + bias[c];
            if (relu) v = fmaxf(v, 0.0f);
            C[(size_t)r * Ncols + c] = v;
        }
    }
}

// ---------------------------------------------------------------------------
// Flash-style attention: per (b,h), 1024 queries x 1024 keys, hd=32.
// Grid (B*H, K/128), 128 threads; thread owns one query; 32-key chunks
// staged through smem; K/V reads are warp-uniform broadcasts (float4).
// ---------------------------------------------------------------------------
__global__ __launch_bounds__(128) void attn_kernel(
    const float* __restrict__ Qb, const float* __restrict__ Kb,
    const float* __restrict__ Vb, float* __restrict__ Ob)
{
    int b = blockIdx.x / Hn;
    int h = blockIdx.x % Hn;
    int qi = blockIdx.y * 128 + threadIdx.x;
    const float scale = 0.17677669529663687f;   // 1/sqrt(32)

    const float* qp = Qb + ((size_t)(b * Kn + qi)) * Dn + h * HDn;
    float q[HDn];
#pragma unroll
    for (int d = 0; d < HDn; d++) q[d] = qp[d] * scale;

    float m = -1e30f, lsum = 0.0f;
    float acc[HDn];
#pragma unroll
    for (int d = 0; d < HDn; d++) acc[d] = 0.0f;

    __shared__ __align__(16) float Ks[32][32];
    __shared__ __align__(16) float Vs[32][32];

    const float* Kbase = Kb + ((size_t)b * Kn) * Dn + h * HDn;
    const float* Vbase = Vb + ((size_t)b * Kn) * Dn + h * HDn;

    for (int kc = 0; kc < Kn; kc += 32) {
        __syncthreads();
#pragma unroll
        for (int i = 0; i < 2; i++) {
            int ee = threadIdx.x + i * 128;      // 0..255 float4 slots
            int r = ee >> 3, c = (ee & 7) << 2;
            *(float4*)&Ks[r][c] = *(const float4*)(Kbase + (size_t)(kc + r) * Dn + c);
            *(float4*)&Vs[r][c] = *(const float4*)(Vbase + (size_t)(kc + r) * Dn + c);
        }
        __syncthreads();

        float s[32];
#pragma unroll
        for (int kk = 0; kk < 32; kk++) {
            float sum = 0.0f;
#pragma unroll
            for (int c = 0; c < 8; c++) {
                float4 kv = *(const float4*)&Ks[kk][c << 2];
                sum += q[4*c]   * kv.x + q[4*c+1] * kv.y
                     + q[4*c+2] * kv.z + q[4*c+3] * kv.w;
            }
            s[kk] = sum;
        }

        float cm = s[0];
#pragma unroll
        for (int kk = 1; kk < 32; kk++) cm = fmaxf(cm, s[kk]);
        float mn = fmaxf(m, cm);
        float alpha = __expf(m - mn);
        lsum *= alpha;
#pragma unroll
        for (int d = 0; d < HDn; d++) acc[d] *= alpha;

#pragma unroll
        for (int kk = 0; kk < 32; kk++) {
            float p = __expf(s[kk] - mn);
            lsum += p;
#pragma unroll
            for (int c = 0; c < 8; c++) {
                float4 vv = *(const float4*)&Vs[kk][c << 2];
                acc[4*c]   += p * vv.x;
                acc[4*c+1] += p * vv.y;
                acc[4*c+2] += p * vv.z;
                acc[4*c+3] += p * vv.w;
            }
        }
        m = mn;
    }

    float inv = 1.0f / lsum;
    float* op = Ob + ((size_t)(b * Kn + qi)) * Dn + h * HDn;
#pragma unroll
    for (int d = 0; d < HDn; d++) op[d] = acc[d] * inv;
}

// ---------------------------------------------------------------------------
// LayerNorm helpers: block of 256 threads, one row of D=256
// ---------------------------------------------------------------------------
__device__ __forceinline__ void block_stats(float v, int t, float& mu, float& rstd)
{
    __shared__ float s1[8], s2[8];
    float su = v, sq = v * v;
#pragma unroll
    for (int o = 16; o; o >>= 1) {
        su += __shfl_down_sync(0xffffffffu, su, o);
        sq += __shfl_down_sync(0xffffffffu, sq, o);
    }
    if ((t & 31) == 0) { s1[t >> 5] = su; s2[t >> 5] = sq; }
    __syncthreads();
    float tsu = 0.0f, tsq = 0.0f;
#pragma unroll
    for (int w = 0; w < 8; w++) { tsu += s1[w]; tsq += s2[w]; }
    mu = tsu * (1.0f / Dn);
    float var = tsq * (1.0f / Dn) - mu * mu;
    rstd = rsqrtf(var + 1e-5f);
}

__global__ __launch_bounds__(256) void ln_add_kernel(
    const float* __restrict__ a, const float* __restrict__ b2,
    const float* __restrict__ gam, const float* __restrict__ bet,
    float* __restrict__ xo)
{
    int row = blockIdx.x, t = threadIdx.x;
    size_t i = (size_t)row * Dn + t;
    float v = a[i] + b2[i];
    float mu, rs;
    block_stats(v, t, mu, rs);
    xo[i] = (v - mu) * rs * gam[t] + bet[t];
}

// LN2 fused with ragged scatter-back: write only rows j < focus_token_nums[b]
__global__ __launch_bounds__(256) void ln2_scatter_kernel(
    const float* __restrict__ a, const float* __restrict__ b2,
    const float* __restrict__ gam, const float* __restrict__ bet,
    float* __restrict__ out, const int* __restrict__ il,
    const int* __restrict__ fnum)
{
    int row = blockIdx.x, t = threadIdx.x;
    int b = row >> 10, j = row & 1023;
    size_t i = (size_t)row * Dn + t;
    float v = a[i] + b2[i];
    float mu, rs;
    block_stats(v, t, mu, rs);
    if (j < fnum[b]) {
        int idx = il[row];
        out[((size_t)b * NN + idx) * Dn + t] = (v - mu) * rs * gam[t] + bet[t];
    }
}

// ---------------------------------------------------------------------------
// Host-side orchestration
// ---------------------------------------------------------------------------
extern "C" void kernel_launch(void* const* d_in, const int* in_sizes, int n_in,
                              void* d_out, int out_size)
{
    // Two plausible input orderings; they coincide for indices >= 5.
    //   setup order:     0 query, 1 query_pos, 2 spatial, 3 lsi, 4 valid, ...
    //   reference order: 0 query, 1 spatial(8), 2 lsi, 3 valid, 4 query_pos, ...
    int qp_idx = (in_sizes[1] == 8) ? 4 : 1;

    const float* query = (const float*)d_in[0];
    const float* qpos  = (const float*)d_in[qp_idx];
    const float* fgs   = (const float*)d_in[6];
    const int*   fnum  = (const int*)d_in[7];
    const int*   inds  = (const int*)d_in[8];
    const float* Wq = (const float*)d_in[9],  *bq = (const float*)d_in[10];
    const float* Wk = (const float*)d_in[11], *bk = (const float*)d_in[12];
    const float* Wv = (const float*)d_in[13], *bv = (const float*)d_in[14];
    const float* Wo = (const float*)d_in[15], *bo = (const float*)d_in[16];
    const float* g1 = (const float*)d_in[17], *be1 = (const float*)d_in[18];
    const float* W1 = (const float*)d_in[19], *b1 = (const float*)d_in[20];
    const float* W2 = (const float*)d_in[21], *b2 = (const float*)d_in[22];
    const float* g2 = (const float*)d_in[23], *be2 = (const float*)d_in[24];
    const float* Wcls = (const float*)d_in[25], *bcls = (const float*)d_in[26];

    float* out = (float*)d_out;

    float* S = nullptr;
    cudaGetSymbolAddress((void**)&S, g_scratch);
    float* tgt = S + OFF_TGT;
    float* qk  = S + OFF_QK;
    float* Qb  = S + OFF_Q;
    float* Kb  = S + OFF_K;
    float* Vb  = S + OFF_V;
    float* Ab  = S + OFF_ATT;
    float* Xb  = S + OFF_X;
    float* Yb  = S + OFF_Y;
    float* Hb  = S + OFF_H;

    // output = query
    cudaMemcpyAsync(out, query, sizeof(float) * (size_t)Bn * NN * Dn,
                    cudaMemcpyDeviceToDevice);

    dim3 gD(Dn / 64, ROWS / 64);       // [4096,256] GEMMs
    dim3 gF(FFNn / 64, ROWS / 64);     // [4096,1024] GEMM

    for (int l = 0; l < L_LAYERS; l++) {
        const int* il = inds + (size_t)l * ROWS;

        gather_cls_kernel<<<ROWS, 256>>>(out, qpos, fgs, il, Wcls, bcls, tgt, qk);

        sgemm64<<<gD, 256>>>(qk,  Wq + (size_t)l * Dn * Dn, bq + l * Dn, Qb, ROWS, Dn, Dn, 0);
        sgemm64<<<gD, 256>>>(qk,  Wk + (size_t)l * Dn * Dn, bk + l * Dn, Kb, ROWS, Dn, Dn, 0);
        sgemm64<<<gD, 256>>>(tgt, Wv + (size_t)l * Dn * Dn, bv + l * Dn, Vb, ROWS, Dn, Dn, 0);

        attn_kernel<<<dim3(Bn * Hn, Kn / 128), 128>>>(Qb, Kb, Vb, Ab);

        sgemm64<<<gD, 256>>>(Ab, Wo + (size_t)l * Dn * Dn, bo + l * Dn, Yb, ROWS, Dn, Dn, 0);

        ln_add_kernel<<<ROWS, 256>>>(tgt, Yb, g1 + l * Dn, be1 + l * Dn, Xb);

        sgemm64<<<gF, 256>>>(Xb, W1 + (size_t)l * Dn * FFNn, b1 + l * FFNn, Hb,
                             ROWS, FFNn, Dn, 1);
        sgemm64<<<gD, 256>>>(Hb, W2 + (size_t)l * FFNn * Dn, b2 + l * Dn, Yb,
                             ROWS, Dn, FFNn, 0);

        ln2_scatter_kernel<<<ROWS, 256>>>(Xb, Yb, g2 + l * Dn, be2 + l * Dn,
                                          out, il, fnum);
    }
}

// round 3
// speedup vs baseline: 1.2999x; 1.2999x over previous
#include <cuda_runtime.h>
#include <cuda_bf16.h>
#include <cstdint>

// ---------------------------------------------------------------------------
// Focus-DETR encoder — round 3: GEMMs on mma.sync bf16 (split-precision x3)
// tcgen05 is unreachable (harness emits compute_103 PTX, no 'a' feature set),
// so tensor work goes through arch-generic HMMA mma.sync.
// L=6, B=4, N=23890, K=1024, D=256, H=8, hd=32, FFN=1024, NCLS=15
// ---------------------------------------------------------------------------

#define L_LAYERS 6
#define Bn 4
#define NN 23890
#define Kn 1024
#define Dn 256
#define Hn 8
#define HDn 32
#define FFNn 1024
#define NCLSn 15

#define ROWS (Bn * Kn)          // 4096
#define RD   (ROWS * Dn)        // 1048576 floats

__device__ float g_scratch[8 * RD + ROWS * FFNn];

#define OFF_TGT 0
#define OFF_QK  (1 * RD)
#define OFF_Q   (2 * RD)
#define OFF_K   (3 * RD)
#define OFF_V   (4 * RD)
#define OFF_ATT (5 * RD)
#define OFF_X   (6 * RD)
#define OFF_Y   (7 * RD)
#define OFF_H   (8 * RD)

// ============================ PTX helpers ==================================

__device__ __forceinline__ uint32_t smem_u32(const void* p) {
    uint32_t a;
    asm("{ .reg .u64 t; cvta.to.shared.u64 t, %1; cvt.u32.u64 %0, t; }"
        : "=r"(a) : "l"(p));
    return a;
}

#define LDSM4(r, addr)                                                          \
    asm volatile("ldmatrix.sync.aligned.m8n8.x4.shared.b16 {%0,%1,%2,%3}, [%4];"\
        : "=r"((r)[0]), "=r"((r)[1]), "=r"((r)[2]), "=r"((r)[3]) : "r"(addr))

#define MMA_BF16(d, a, b0, b1)                                                  \
    asm volatile("mma.sync.aligned.m16n8k16.row.col.f32.bf16.bf16.f32 "         \
        "{%0,%1,%2,%3}, {%4,%5,%6,%7}, {%8,%9}, {%0,%1,%2,%3};"                 \
        : "+f"((d)[0]), "+f"((d)[1]), "+f"((d)[2]), "+f"((d)[3])                \
        : "r"((a)[0]), "r"((a)[1]), "r"((a)[2]), "r"((a)[3]), "r"(b0), "r"(b1))

// ============================ bf16x3 GEMM ==================================
// C[4096, Ncols] = A[4096, Kd] @ W[Kd, Ncols] + bias (+ReLU)
// CTA: 256 threads (8 warps as 2M x 4N), tile 128x128, K-chunk 32.
// SMEM tiles: bf16, rows padded to 40 elems (80B) -> conflict-free ldmatrix.
//   Ah @ 0, Al @ 10240, Bh @ 20480, Bl @ 30720   (total 40960 B)
// B stored transposed: Bs[n][k].
// Split: v = hi + lo (bf16 each); products hi*hi + lo*hi + hi*lo.
// ---------------------------------------------------------------------------

#define GB_AH 0
#define GB_AL 10240
#define GB_BH 20480
#define GB_BL 30720
#define GB_SMEM 40960

__global__ __launch_bounds__(256, 1)
void gemm_bf16(const float* __restrict__ A, const float* __restrict__ W,
               const float* __restrict__ bias, float* __restrict__ C,
               int Ncols, int Kd, int relu)
{
    extern __shared__ __align__(16) char smem[];
    const uint32_t sb = smem_u32(smem);

    const int tid  = threadIdx.x;
    const int lane = tid & 31;
    const int wid  = tid >> 5;
    const int wm   = wid & 1;          // 0..1  (M)
    const int wn   = wid >> 1;         // 0..3  (N)
    const int bm   = blockIdx.y << 7;
    const int bn   = blockIdx.x << 7;

    float acc[4][4][4];
#pragma unroll
    for (int i = 0; i < 4; i++)
#pragma unroll
        for (int j = 0; j < 4; j++)
#pragma unroll
            for (int q = 0; q < 4; q++) acc[i][j][q] = 0.0f;

    // ldmatrix per-thread address components
    const int a_r = wm * 64 + (lane & 15);
    const int a_c = (lane >> 4) << 3;
    const int b_r = wn * 32 + (lane & 7) + ((lane >> 4) << 3);
    const int b_c = ((lane >> 3) & 1) << 3;

    // global load mapping
    const int a_row = tid >> 3;            // 0..31 (+p*32)
    const int a_kq  = tid & 7;             // float4 slot in k
    const int b_n   = tid & 127;
    const int b_kb  = (tid >> 7) << 4;     // 0 or 16

    const float* Ap0 = A + (size_t)(bm + a_row) * Kd + (a_kq << 2);
    const float* Wp0 = W + (size_t)b_kb * Ncols + bn + b_n;

    const int nc = Kd >> 5;

    float4 av[4];
    float  bv[16];

    // prefetch chunk 0
#pragma unroll
    for (int p = 0; p < 4; p++)
        av[p] = *(const float4*)(Ap0 + (size_t)(p << 5) * Kd);
#pragma unroll
    for (int i = 0; i < 16; i++)
        bv[i] = Wp0[(size_t)i * Ncols];

    for (int c = 0; c < nc; c++) {
        // ---- convert + store to smem ----
#pragma unroll
        for (int p = 0; p < 4; p++) {
            int row = a_row + (p << 5);
            uint32_t off = (uint32_t)(row * 40 + (a_kq << 2)) * 2;
            float4 v = av[p];
            __nv_bfloat16 hx = __float2bfloat16(v.x);
            __nv_bfloat16 hy = __float2bfloat16(v.y);
            __nv_bfloat16 hz = __float2bfloat16(v.z);
            __nv_bfloat16 hw = __float2bfloat16(v.w);
            *(__nv_bfloat162*)(smem + GB_AH + off)     = __halves2bfloat162(hx, hy);
            *(__nv_bfloat162*)(smem + GB_AH + off + 4) = __halves2bfloat162(hz, hw);
            __nv_bfloat16 lx = __float2bfloat16(v.x - __bfloat162float(hx));
            __nv_bfloat16 ly = __float2bfloat16(v.y - __bfloat162float(hy));
            __nv_bfloat16 lz = __float2bfloat16(v.z - __bfloat162float(hz));
            __nv_bfloat16 lw = __float2bfloat16(v.w - __bfloat162float(hw));
            *(__nv_bfloat162*)(smem + GB_AL + off)     = __halves2bfloat162(lx, ly);
            *(__nv_bfloat162*)(smem + GB_AL + off + 4) = __halves2bfloat162(lz, lw);
        }
#pragma unroll
        for (int i = 0; i < 8; i++) {
            uint32_t off = (uint32_t)(b_n * 40 + b_kb + (i << 1)) * 2;
            float v0 = bv[2 * i], v1 = bv[2 * i + 1];
            __nv_bfloat16 h0 = __float2bfloat16(v0);
            __nv_bfloat16 h1 = __float2bfloat16(v1);
            *(__nv_bfloat162*)(smem + GB_BH + off) = __halves2bfloat162(h0, h1);
            __nv_bfloat16 l0 = __float2bfloat16(v0 - __bfloat162float(h0));
            __nv_bfloat16 l1 = __float2bfloat16(v1 - __bfloat162float(h1));
            *(__nv_bfloat162*)(smem + GB_BL + off) = __halves2bfloat162(l0, l1);
        }
        __syncthreads();

        // ---- prefetch next chunk while mma runs ----
        if (c + 1 < nc) {
            const int k0 = (c + 1) << 5;
#pragma unroll
            for (int p = 0; p < 4; p++)
                av[p] = *(const float4*)(Ap0 + (size_t)(p << 5) * Kd + k0);
            const float* Wp = Wp0 + (size_t)k0 * Ncols;
#pragma unroll
            for (int i = 0; i < 16; i++)
                bv[i] = Wp[(size_t)i * Ncols];
        }

        // ---- mma on this chunk ----
#pragma unroll
        for (int ks = 0; ks < 2; ks++) {
            uint32_t ah[4][4], al[4][4];
#pragma unroll
            for (int mb = 0; mb < 4; mb++) {
                uint32_t ao = (uint32_t)((a_r + mb * 16) * 40 + ks * 16 + a_c) * 2;
                LDSM4(ah[mb], sb + GB_AH + ao);
                LDSM4(al[mb], sb + GB_AL + ao);
            }
            uint32_t bh[2][4], bl[2][4];
#pragma unroll
            for (int np = 0; np < 2; np++) {
                uint32_t bo = (uint32_t)((b_r + np * 16) * 40 + ks * 16 + b_c) * 2;
                LDSM4(bh[np], sb + GB_BH + bo);
                LDSM4(bl[np], sb + GB_BL + bo);
            }
#pragma unroll
            for (int mb = 0; mb < 4; mb++)
#pragma unroll
                for (int nb = 0; nb < 4; nb++) {
                    const int np = nb >> 1, sl = (nb & 1) << 1;
                    MMA_BF16(acc[mb][nb], ah[mb], bh[np][sl], bh[np][sl + 1]);
                    MMA_BF16(acc[mb][nb], al[mb], bh[np][sl], bh[np][sl + 1]);
                    MMA_BF16(acc[mb][nb], ah[mb], bl[np][sl], bl[np][sl + 1]);
                }
        }
        __syncthreads();
    }

    // ---- epilogue: bias (+relu), fp32 stores ----
    const int r0 = bm + wm * 64 + (lane >> 2);
    const int c0 = bn + wn * 32 + ((lane & 3) << 1);
#pragma unroll
    for (int mb = 0; mb < 4; mb++) {
#pragma unroll
        for (int nb = 0; nb < 4; nb++) {
            int rr = r0 + mb * 16, cc = c0 + nb * 8;
            float bb0 = bias[cc], bb1 = bias[cc + 1];
            float2 v0, v1;
            v0.x = acc[mb][nb][0] + bb0; v0.y = acc[mb][nb][1] + bb1;
            v1.x = acc[mb][nb][2] + bb0; v1.y = acc[mb][nb][3] + bb1;
            if (relu) {
                v0.x = fmaxf(v0.x, 0.f); v0.y = fmaxf(v0.y, 0.f);
                v1.x = fmaxf(v1.x, 0.f); v1.y = fmaxf(v1.y, 0.f);
            }
            *(float2*)(C + (size_t)rr * Ncols + cc)       = v0;
            *(float2*)(C + (size_t)(rr + 8) * Ncols + cc) = v1;
        }
    }
}

// ---------------------------------------------------------------------------
// Gather + MCSP score modulation
// ---------------------------------------------------------------------------
__global__ __launch_bounds__(256) void gather_cls_kernel(
    const float* __restrict__ out, const float* __restrict__ qpos,
    const float* __restrict__ fgs, const int* __restrict__ il,
    const float* __restrict__ Wcls, const float* __restrict__ bcls,
    float* __restrict__ tgt, float* __restrict__ qk)
{
    int row = blockIdx.x;
    int b   = row >> 10;
    int t   = threadIdx.x;
    int idx = il[row];
    size_t src = ((size_t)b * NN + idx) * Dn + t;
    float qv = out[src];

    float part[NCLSn];
#pragma unroll
    for (int c = 0; c < NCLSn; c++) part[c] = qv * Wcls[t * NCLSn + c];

    __shared__ float red[8][NCLSn];
#pragma unroll
    for (int c = 0; c < NCLSn; c++) {
        float v = part[c];
#pragma unroll
        for (int o = 16; o; o >>= 1) v += __shfl_down_sync(0xffffffffu, v, o);
        if ((t & 31) == 0) red[t >> 5][c] = v;
    }
    __syncthreads();

    __shared__ float s_mc;
    if (t == 0) {
        float mx = -1e30f;
#pragma unroll
        for (int c = 0; c < NCLSn; c++) {
            float sum = bcls[c];
#pragma unroll
            for (int w = 0; w < 8; w++) sum += red[w][c];
            mx = fmaxf(mx, sum);
        }
        float sig = 1.0f / (1.0f + __expf(-mx));
        s_mc = sig * fgs[(size_t)b * NN + idx];
    }
    __syncthreads();

    float tv = qv * s_mc;
    tgt[(size_t)row * Dn + t] = tv;
    qk[(size_t)row * Dn + t]  = tv + qpos[src];
}

// ---------------------------------------------------------------------------
// Flash-style attention (fp32)
// ---------------------------------------------------------------------------
__global__ __launch_bounds__(128) void attn_kernel(
    const float* __restrict__ Qb, const float* __restrict__ Kb,
    const float* __restrict__ Vb, float* __restrict__ Ob)
{
    int b = blockIdx.x / Hn;
    int h = blockIdx.x % Hn;
    int qi = blockIdx.y * 128 + threadIdx.x;
    const float scale = 0.17677669529663687f;

    const float* qp = Qb + ((size_t)(b * Kn + qi)) * Dn + h * HDn;
    float q[HDn];
#pragma unroll
    for (int d = 0; d < HDn; d++) q[d] = qp[d] * scale;

    float m = -1e30f, lsum = 0.0f;
    float acc[HDn];
#pragma unroll
    for (int d = 0; d < HDn; d++) acc[d] = 0.0f;

    __shared__ __align__(16) float Ks[32][32];
    __shared__ __align__(16) float Vs[32][32];

    const float* Kbase = Kb + ((size_t)b * Kn) * Dn + h * HDn;
    const float* Vbase = Vb + ((size_t)b * Kn) * Dn + h * HDn;

    for (int kc = 0; kc < Kn; kc += 32) {
        __syncthreads();
#pragma unroll
        for (int i = 0; i < 2; i++) {
            int ee = threadIdx.x + i * 128;
            int r = ee >> 3, c = (ee & 7) << 2;
            *(float4*)&Ks[r][c] = *(const float4*)(Kbase + (size_t)(kc + r) * Dn + c);
            *(float4*)&Vs[r][c] = *(const float4*)(Vbase + (size_t)(kc + r) * Dn + c);
        }
        __syncthreads();

        float s[32];
#pragma unroll
        for (int kk = 0; kk < 32; kk++) {
            float sum = 0.0f;
#pragma unroll
            for (int c = 0; c < 8; c++) {
                float4 kv = *(const float4*)&Ks[kk][c << 2];
                sum += q[4*c]   * kv.x + q[4*c+1] * kv.y
                     + q[4*c+2] * kv.z + q[4*c+3] * kv.w;
            }
            s[kk] = sum;
        }

        float cm = s[0];
#pragma unroll
        for (int kk = 1; kk < 32; kk++) cm = fmaxf(cm, s[kk]);
        float mn = fmaxf(m, cm);
        float alpha = __expf(m - mn);
        lsum *= alpha;
#pragma unroll
        for (int d = 0; d < HDn; d++) acc[d] *= alpha;

#pragma unroll
        for (int kk = 0; kk < 32; kk++) {
            float p = __expf(s[kk] - mn);
            lsum += p;
#pragma unroll
            for (int c = 0; c < 8; c++) {
                float4 vv = *(const float4*)&Vs[kk][c << 2];
                acc[4*c]   += p * vv.x;
                acc[4*c+1] += p * vv.y;
                acc[4*c+2] += p * vv.z;
                acc[4*c+3] += p * vv.w;
            }
        }
        m = mn;
    }

    float inv = 1.0f / lsum;
    float* op = Ob + ((size_t)(b * Kn + qi)) * Dn + h * HDn;
#pragma unroll
    for (int d = 0; d < HDn; d++) op[d] = acc[d] * inv;
}

// ---------------------------------------------------------------------------
// LayerNorm kernels
// ---------------------------------------------------------------------------
__device__ __forceinline__ void block_stats(float v, int t, float& mu, float& rstd)
{
    __shared__ float s1[8], s2[8];
    float su = v, sq = v * v;
#pragma unroll
    for (int o = 16; o; o >>= 1) {
        su += __shfl_down_sync(0xffffffffu, su, o);
        sq += __shfl_down_sync(0xffffffffu, sq, o);
    }
    if ((t & 31) == 0) { s1[t >> 5] = su; s2[t >> 5] = sq; }
    __syncthreads();
    float tsu = 0.0f, tsq = 0.0f;
#pragma unroll
    for (int w = 0; w < 8; w++) { tsu += s1[w]; tsq += s2[w]; }
    mu = tsu * (1.0f / Dn);
    float var = tsq * (1.0f / Dn) - mu * mu;
    rstd = rsqrtf(var + 1e-5f);
}

__global__ __launch_bounds__(256) void ln_add_kernel(
    const float* __restrict__ a, const float* __restrict__ b2,
    const float* __restrict__ gam, const float* __restrict__ bet,
    float* __restrict__ xo)
{
    int row = blockIdx.x, t = threadIdx.x;
    size_t i = (size_t)row * Dn + t;
    float v = a[i] + b2[i];
    float mu, rs;
    block_stats(v, t, mu, rs);
    xo[i] = (v - mu) * rs * gam[t] + bet[t];
}

__global__ __launch_bounds__(256) void ln2_scatter_kernel(
    const float* __restrict__ a, const float* __restrict__ b2,
    const float* __restrict__ gam, const float* __restrict__ bet,
    float* __restrict__ out, const int* __restrict__ il,
    const int* __restrict__ fnum)
{
    int row = blockIdx.x, t = threadIdx.x;
    int b = row >> 10, j = row & 1023;
    size_t i = (size_t)row * Dn + t;
    float v = a[i] + b2[i];
    float mu, rs;
    block_stats(v, t, mu, rs);
    if (j < fnum[b]) {
        int idx = il[row];
        out[((size_t)b * NN + idx) * Dn + t] = (v - mu) * rs * gam[t] + bet[t];
    }
}

// ---------------------------------------------------------------------------
// Host-side orchestration
// ---------------------------------------------------------------------------
extern "C" void kernel_launch(void* const* d_in, const int* in_sizes, int n_in,
                              void* d_out, int out_size)
{
    int qp_idx = (in_sizes[1] == 8) ? 4 : 1;

    const float* query = (const float*)d_in[0];
    const float* qpos  = (const float*)d_in[qp_idx];
    const float* fgs   = (const float*)d_in[6];
    const int*   fnum  = (const int*)d_in[7];
    const int*   inds  = (const int*)d_in[8];
    const float* Wq = (const float*)d_in[9],  *bq = (const float*)d_in[10];
    const float* Wk = (const float*)d_in[11], *bk = (const float*)d_in[12];
    const float* Wv = (const float*)d_in[13], *bv = (const float*)d_in[14];
    const float* Wo = (const float*)d_in[15], *bo = (const float*)d_in[16];
    const float* g1 = (const float*)d_in[17], *be1 = (const float*)d_in[18];
    const float* W1 = (const float*)d_in[19], *b1 = (const float*)d_in[20];
    const float* W2 = (const float*)d_in[21], *b2 = (const float*)d_in[22];
    const float* g2 = (const float*)d_in[23], *be2 = (const float*)d_in[24];
    const float* Wcls = (const float*)d_in[25], *bcls = (const float*)d_in[26];

    float* out = (float*)d_out;

    float* S = nullptr;
    cudaGetSymbolAddress((void**)&S, g_scratch);
    float* tgt = S + OFF_TGT;
    float* qk  = S + OFF_QK;
    float* Qb  = S + OFF_Q;
    float* Kb  = S + OFF_K;
    float* Vb  = S + OFF_V;
    float* Ab  = S + OFF_ATT;
    float* Xb  = S + OFF_X;
    float* Yb  = S + OFF_Y;
    float* Hb  = S + OFF_H;

    cudaMemcpyAsync(out, query, sizeof(float) * (size_t)Bn * NN * Dn,
                    cudaMemcpyDeviceToDevice);

    dim3 gD(Dn / 128, ROWS / 128);      // (2, 32)
    dim3 gF(FFNn / 128, ROWS / 128);    // (8, 32)

    for (int l = 0; l < L_LAYERS; l++) {
        const int* il = inds + (size_t)l * ROWS;

        gather_cls_kernel<<<ROWS, 256>>>(out, qpos, fgs, il, Wcls, bcls, tgt, qk);

        gemm_bf16<<<gD, 256, GB_SMEM>>>(qk,  Wq + (size_t)l * Dn * Dn, bq + l * Dn, Qb, Dn, Dn, 0);
        gemm_bf16<<<gD, 256, GB_SMEM>>>(qk,  Wk + (size_t)l * Dn * Dn, bk + l * Dn, Kb, Dn, Dn, 0);
        gemm_bf16<<<gD, 256, GB_SMEM>>>(tgt, Wv + (size_t)l * Dn * Dn, bv + l * Dn, Vb, Dn, Dn, 0);

        attn_kernel<<<dim3(Bn * Hn, Kn / 128), 128>>>(Qb, Kb, Vb, Ab);

        gemm_bf16<<<gD, 256, GB_SMEM>>>(Ab, Wo + (size_t)l * Dn * Dn, bo + l * Dn, Yb, Dn, Dn, 0);

        ln_add_kernel<<<ROWS, 256>>>(tgt, Yb, g1 + l * Dn, be1 + l * Dn, Xb);

        gemm_bf16<<<gF, 256, GB_SMEM>>>(Xb, W1 + (size_t)l * Dn * FFNn, b1 + l * FFNn, Hb,
                                        FFNn, Dn, 1);
        gemm_bf16<<<gD, 256, GB_SMEM>>>(Hb, W2 + (size_t)l * FFNn * Dn, b2 + l * Dn, Yb,
                                        Dn, FFNn, 0);

        ln2_scatter_kernel<<<ROWS, 256>>>(Xb, Yb, g2 + l * Dn, be2 + l * Dn,
                                          out, il, fnum);
    }
}

// round 4
// speedup vs baseline: 1.4288x; 1.0992x over previous
#include <cuda_runtime.h>
#include <cuda_bf16.h>
#include <cstdint>

// ---------------------------------------------------------------------------
// Focus-DETR encoder — round 4: lean bf16x3 GEMM (pre-split operands,
// cp.async double buffering, batched QKV). tcgen05 unavailable (compute_103).
// ---------------------------------------------------------------------------

#define L_LAYERS 6
#define Bn 4
#define NN 23890
#define Kn 1024
#define Dn 256
#define Hn 8
#define HDn 32
#define FFNn 1024
#define NCLSn 15

#define ROWS (Bn * Kn)          // 4096
#define RD   (ROWS * Dn)        // 1048576 elements

// ---------------- scratch carving (single __device__ arena) ----------------
constexpr size_t SZ_F  = (size_t)RD * 4;              // fp32 [4096][256]
constexpr size_t SZ_B  = (size_t)RD * 2;              // bf16 [4096][256]
constexpr size_t SZ_H  = (size_t)ROWS * FFNn * 2;     // bf16 [4096][1024]
constexpr size_t SZ_WD = (size_t)L_LAYERS * Dn * Dn * 2;
constexpr size_t SZ_W1 = (size_t)L_LAYERS * Dn * FFNn * 2;

constexpr size_t OF_TGT = 0;
constexpr size_t OF_QB  = OF_TGT + SZ_F;
constexpr size_t OF_KB  = OF_QB  + SZ_F;
constexpr size_t OF_VB  = OF_KB  + SZ_F;
constexpr size_t OF_XB  = OF_VB  + SZ_F;
constexpr size_t OF_YB  = OF_XB  + SZ_F;
constexpr size_t OF_QKH = OF_YB  + SZ_F;
constexpr size_t OF_QKL = OF_QKH + SZ_B;
constexpr size_t OF_TGH = OF_QKL + SZ_B;
constexpr size_t OF_TGL = OF_TGH + SZ_B;
constexpr size_t OF_ATH = OF_TGL + SZ_B;
constexpr size_t OF_ATL = OF_ATH + SZ_B;
constexpr size_t OF_XH  = OF_ATL + SZ_B;
constexpr size_t OF_XL  = OF_XH  + SZ_B;
constexpr size_t OF_HH  = OF_XL  + SZ_B;
constexpr size_t OF_HL  = OF_HH  + SZ_H;
constexpr size_t OF_WQH = OF_HL  + SZ_H;
constexpr size_t OF_WQL = OF_WQH + SZ_WD;
constexpr size_t OF_WKH = OF_WQL + SZ_WD;
constexpr size_t OF_WKL = OF_WKH + SZ_WD;
constexpr size_t OF_WVH = OF_WKL + SZ_WD;
constexpr size_t OF_WVL = OF_WVH + SZ_WD;
constexpr size_t OF_WOH = OF_WVL + SZ_WD;
constexpr size_t OF_WOL = OF_WOH + SZ_WD;
constexpr size_t OF_W1H = OF_WOL + SZ_WD;
constexpr size_t OF_W1L = OF_W1H + SZ_W1;
constexpr size_t OF_W2H = OF_W1L + SZ_W1;
constexpr size_t OF_W2L = OF_W2H + SZ_W1;
constexpr size_t G_TOTAL = OF_W2L + SZ_W1;

__device__ __align__(1024) unsigned char g_mem[G_TOTAL];

// ============================ PTX helpers ==================================

__device__ __forceinline__ uint32_t smem_u32(const void* p) {
    uint32_t a;
    asm("{ .reg .u64 t; cvta.to.shared.u64 t, %1; cvt.u32.u64 %0, t; }"
        : "=r"(a) : "l"(p));
    return a;
}

#define CP16(sa, ga)                                                            \
    asm volatile("cp.async.ca.shared.global [%0], [%1], 16;"                    \
                 :: "r"(sa), "l"(__cvta_generic_to_global(ga)))
#define CP_COMMIT() asm volatile("cp.async.commit_group;" ::: "memory")
#define CP_WAIT0()  asm volatile("cp.async.wait_group 0;" ::: "memory")
#define CP_WAIT1()  asm volatile("cp.async.wait_group 1;" ::: "memory")

#define LDSM4(r, addr)                                                          \
    asm volatile("ldmatrix.sync.aligned.m8n8.x4.shared.b16 {%0,%1,%2,%3}, [%4];"\
        : "=r"((r)[0]), "=r"((r)[1]), "=r"((r)[2]), "=r"((r)[3]) : "r"(addr))

#define MMA_BF16(d, a, b0, b1)                                                  \
    asm volatile("mma.sync.aligned.m16n8k16.row.col.f32.bf16.bf16.f32 "         \
        "{%0,%1,%2,%3}, {%4,%5,%6,%7}, {%8,%9}, {%0,%1,%2,%3};"                 \
        : "+f"((d)[0]), "+f"((d)[1]), "+f"((d)[2]), "+f"((d)[3])                \
        : "r"((a)[0]), "r"((a)[1]), "r"((a)[2]), "r"((a)[3]), "r"(b0), "r"(b1))

__device__ __forceinline__ void split_bf16(float v, __nv_bfloat16& h, __nv_bfloat16& l) {
    h = __float2bfloat16(v);
    l = __float2bfloat16(v - __bfloat162float(h));
}

// ===================== weight prep: transpose + split ======================
// W[L][Kd][Ncols] -> Wt_h/l[L][Ncols][Kd] (bf16, k contiguous)
__global__ __launch_bounds__(256) void wprep(
    const float* __restrict__ W, __nv_bfloat16* __restrict__ Wh,
    __nv_bfloat16* __restrict__ Wl, int Kd, int Ncols)
{
    __shared__ float tile[32][33];
    const int l  = blockIdx.z;
    const int k0 = blockIdx.x << 5, n0 = blockIdx.y << 5;
    const int tx = threadIdx.x & 31, ty = threadIdx.x >> 5;   // 32x8

    const float* Wp = W + (size_t)l * Kd * Ncols;
#pragma unroll
    for (int r = ty; r < 32; r += 8)
        tile[r][tx] = Wp[(size_t)(k0 + r) * Ncols + n0 + tx];
    __syncthreads();

    __nv_bfloat16* Hp = Wh + ((size_t)l * Ncols + n0) * Kd + k0;
    __nv_bfloat16* Lp = Wl + ((size_t)l * Ncols + n0) * Kd + k0;
#pragma unroll
    for (int r = ty; r < 32; r += 8) {
        float v = tile[tx][r];              // k = k0+tx, n = n0+r
        __nv_bfloat16 h, lo; split_bf16(v, h, lo);
        Hp[(size_t)r * Kd + tx] = h;
        Lp[(size_t)r * Kd + tx] = lo;
    }
}

// ============================ bf16x3 GEMM v2 ===============================
// C[4096, Ncols] = A @ W^T(+bias); A,W pre-split bf16 hi/lo, k-contiguous.
// Tile 64x128, 128 threads (4 warps, 1M x 4N), K-chunk 32, cp.async x2 buf.
// mode 0: fp32 out;  mode 2: relu + bf16 hi/lo out.
// ---------------------------------------------------------------------------
struct GemmP {
    const __nv_bfloat16 *Ah[3], *Al[3], *Wh[3], *Wl[3];
    const float* bias[3];
    float* C[3];
    __nv_bfloat16 *Ch[3], *Cl[3];
};

#define G2_AH 0
#define G2_AL 5120
#define G2_BH 10240
#define G2_BL 20480
#define G2_BUF 30720
#define G2_SMEM (2 * G2_BUF)

__global__ __launch_bounds__(128) void gemm2(GemmP p, int Ncols, int Kd, int mode)
{
    extern __shared__ __align__(16) char smem[];
    const uint32_t sb = smem_u32(smem);

    const int z    = blockIdx.z;
    const __nv_bfloat16* Ah = p.Ah[z];
    const __nv_bfloat16* Al = p.Al[z];
    const __nv_bfloat16* Wh = p.Wh[z];
    const __nv_bfloat16* Wl = p.Wl[z];

    const int tid  = threadIdx.x;
    const int lane = tid & 31;
    const int wn   = tid >> 5;          // warp -> N quadrant
    const int bm   = blockIdx.y << 6;
    const int bn   = blockIdx.x << 7;

    float acc[4][4][4];
#pragma unroll
    for (int i = 0; i < 4; i++)
#pragma unroll
        for (int j = 0; j < 4; j++)
#pragma unroll
            for (int q = 0; q < 4; q++) acc[i][j][q] = 0.0f;

    const int a_r = lane & 15;
    const int a_c = (lane >> 4) << 3;
    const int b_r = wn * 32 + (lane & 7) + ((lane >> 4) << 3);
    const int b_c = ((lane >> 3) & 1) << 3;

    const int nc = Kd >> 5;

    // ---- cp.async chunk issue ----
    auto issue = [&](int c, int buf) {
        const uint32_t sa = sb + buf * G2_BUF;
        const size_t kb = (size_t)(c << 5) * 2;     // byte offset along k
#pragma unroll
        for (int i = 0; i < 2; i++) {               // A: 64 rows x 4 segs
            int s = tid + (i << 7);
            int row = s >> 2, seg = s & 3;
            size_t go = ((size_t)(bm + row) * Kd) * 2 + kb + seg * 16;
            uint32_t so = sa + row * 80 + seg * 16;
            CP16(so + G2_AH, (const char*)Ah + go);
            CP16(so + G2_AL, (const char*)Al + go);
        }
#pragma unroll
        for (int i = 0; i < 4; i++) {               // B: 128 rows x 4 segs
            int s = tid + (i << 7);
            int row = s >> 2, seg = s & 3;
            size_t go = ((size_t)(bn + row) * Kd) * 2 + kb + seg * 16;
            uint32_t so = sa + row * 80 + seg * 16;
            CP16(so + G2_BH, (const char*)Wh + go);
            CP16(so + G2_BL, (const char*)Wl + go);
        }
        CP_COMMIT();
    };

    issue(0, 0);

    for (int c = 0; c < nc; c++) {
        const int buf = c & 1;
        if (c + 1 < nc) { issue(c + 1, buf ^ 1); CP_WAIT1(); }
        else           { CP_WAIT0(); }
        __syncthreads();

        const uint32_t sa = sb + buf * G2_BUF;
#pragma unroll
        for (int ks = 0; ks < 2; ks++) {
            uint32_t ah[4][4], al[4][4];
#pragma unroll
            for (int mb = 0; mb < 4; mb++) {
                uint32_t ao = sa + (uint32_t)(a_r + mb * 16) * 80 + (ks * 16 + a_c) * 2;
                LDSM4(ah[mb], ao + G2_AH);
                LDSM4(al[mb], ao + G2_AL);
            }
            uint32_t bh[2][4], bl[2][4];
#pragma unroll
            for (int np = 0; np < 2; np++) {
                uint32_t bo = sa + (uint32_t)(b_r + np * 16) * 80 + (ks * 16 + b_c) * 2;
                LDSM4(bh[np], bo + G2_BH);
                LDSM4(bl[np], bo + G2_BL);
            }
#pragma unroll
            for (int mb = 0; mb < 4; mb++)
#pragma unroll
                for (int nb = 0; nb < 4; nb++) {
                    const int np = nb >> 1, sl = (nb & 1) << 1;
                    MMA_BF16(acc[mb][nb], ah[mb], bh[np][sl], bh[np][sl + 1]);
                    MMA_BF16(acc[mb][nb], al[mb], bh[np][sl], bh[np][sl + 1]);
                    MMA_BF16(acc[mb][nb], ah[mb], bl[np][sl], bl[np][sl + 1]);
                }
        }
        __syncthreads();
    }

    // ---- epilogue ----
    const float* bias = p.bias[z];
    const int r0 = bm + (lane >> 2);
    const int c0 = bn + wn * 32 + ((lane & 3) << 1);

    if (mode == 0) {
        float* C = p.C[z];
#pragma unroll
        for (int mb = 0; mb < 4; mb++)
#pragma unroll
            for (int nb = 0; nb < 4; nb++) {
                int rr = r0 + mb * 16, cc = c0 + nb * 8;
                float bb0 = bias[cc], bb1 = bias[cc + 1];
                float2 v0, v1;
                v0.x = acc[mb][nb][0] + bb0; v0.y = acc[mb][nb][1] + bb1;
                v1.x = acc[mb][nb][2] + bb0; v1.y = acc[mb][nb][3] + bb1;
                *(float2*)(C + (size_t)rr * Ncols + cc)       = v0;
                *(float2*)(C + (size_t)(rr + 8) * Ncols + cc) = v1;
            }
    } else {
        __nv_bfloat16* Ch = p.Ch[z];
        __nv_bfloat16* Cl = p.Cl[z];
#pragma unroll
        for (int mb = 0; mb < 4; mb++)
#pragma unroll
            for (int nb = 0; nb < 4; nb++) {
                int rr = r0 + mb * 16, cc = c0 + nb * 8;
                float bb0 = bias[cc], bb1 = bias[cc + 1];
#pragma unroll
                for (int hrow = 0; hrow < 2; hrow++) {
                    int r = rr + hrow * 8;
                    float v0 = fmaxf(acc[mb][nb][2 * hrow]     + bb0, 0.0f);
                    float v1 = fmaxf(acc[mb][nb][2 * hrow + 1] + bb1, 0.0f);
                    __nv_bfloat16 h0, l0, h1, l1;
                    split_bf16(v0, h0, l0);
                    split_bf16(v1, h1, l1);
                    *(__nv_bfloat162*)(Ch + (size_t)r * Ncols + cc) = __halves2bfloat162(h0, h1);
                    *(__nv_bfloat162*)(Cl + (size_t)r * Ncols + cc) = __halves2bfloat162(l0, l1);
                }
            }
    }
}

// ---------------------------------------------------------------------------
// Gather + MCSP: writes tgt fp32 + tgt hi/lo + qk hi/lo
// ---------------------------------------------------------------------------
__global__ __launch_bounds__(256) void gather_cls_kernel(
    const float* __restrict__ out, const float* __restrict__ qpos,
    const float* __restrict__ fgs, const int* __restrict__ il,
    const float* __restrict__ Wcls, const float* __restrict__ bcls,
    float* __restrict__ tgt,
    __nv_bfloat16* __restrict__ tgh, __nv_bfloat16* __restrict__ tgl,
    __nv_bfloat16* __restrict__ qkh, __nv_bfloat16* __restrict__ qkl)
{
    int row = blockIdx.x;
    int b   = row >> 10;
    int t   = threadIdx.x;
    int idx = il[row];
    size_t src = ((size_t)b * NN + idx) * Dn + t;
    float qv = out[src];

    float part[NCLSn];
#pragma unroll
    for (int c = 0; c < NCLSn; c++) part[c] = qv * Wcls[t * NCLSn + c];

    __shared__ float red[8][NCLSn];
#pragma unroll
    for (int c = 0; c < NCLSn; c++) {
        float v = part[c];
#pragma unroll
        for (int o = 16; o; o >>= 1) v += __shfl_down_sync(0xffffffffu, v, o);
        if ((t & 31) == 0) red[t >> 5][c] = v;
    }
    __syncthreads();

    __shared__ float s_mc;
    if (t == 0) {
        float mx = -1e30f;
#pragma unroll
        for (int c = 0; c < NCLSn; c++) {
            float sum = bcls[c];
#pragma unroll
            for (int w = 0; w < 8; w++) sum += red[w][c];
            mx = fmaxf(mx, sum);
        }
        float sig = 1.0f / (1.0f + __expf(-mx));
        s_mc = sig * fgs[(size_t)b * NN + idx];
    }
    __syncthreads();

    float tv = tgt[(size_t)row * Dn + t] = qv * s_mc;
    float qk = tv + qpos[src];
    size_t i = (size_t)row * Dn + t;
    __nv_bfloat16 h, lo;
    split_bf16(tv, h, lo); tgh[i] = h; tgl[i] = lo;
    split_bf16(qk, h, lo); qkh[i] = h; qkl[i] = lo;
}

// ---------------------------------------------------------------------------
// Flash-style attention (fp32 in, bf16 hi/lo out)
// ---------------------------------------------------------------------------
__global__ __launch_bounds__(128) void attn_kernel(
    const float* __restrict__ Qb, const float* __restrict__ Kb,
    const float* __restrict__ Vb,
    __nv_bfloat16* __restrict__ Oh, __nv_bfloat16* __restrict__ Ol)
{
    int b = blockIdx.x / Hn;
    int h = blockIdx.x % Hn;
    int qi = blockIdx.y * 128 + threadIdx.x;
    const float scale = 0.17677669529663687f;

    const float* qp = Qb + ((size_t)(b * Kn + qi)) * Dn + h * HDn;
    float q[HDn];
#pragma unroll
    for (int d = 0; d < HDn; d++) q[d] = qp[d] * scale;

    float m = -1e30f, lsum = 0.0f;
    float acc[HDn];
#pragma unroll
    for (int d = 0; d < HDn; d++) acc[d] = 0.0f;

    __shared__ __align__(16) float Ks[32][32];
    __shared__ __align__(16) float Vs[32][32];

    const float* Kbase = Kb + ((size_t)b * Kn) * Dn + h * HDn;
    const float* Vbase = Vb + ((size_t)b * Kn) * Dn + h * HDn;

    for (int kc = 0; kc < Kn; kc += 32) {
        __syncthreads();
#pragma unroll
        for (int i = 0; i < 2; i++) {
            int ee = threadIdx.x + i * 128;
            int r = ee >> 3, c = (ee & 7) << 2;
            *(float4*)&Ks[r][c] = *(const float4*)(Kbase + (size_t)(kc + r) * Dn + c);
            *(float4*)&Vs[r][c] = *(const float4*)(Vbase + (size_t)(kc + r) * Dn + c);
        }
        __syncthreads();

        float s[32];
#pragma unroll
        for (int kk = 0; kk < 32; kk++) {
            float sum = 0.0f;
#pragma unroll
            for (int c = 0; c < 8; c++) {
                float4 kv = *(const float4*)&Ks[kk][c << 2];
                sum += q[4*c]   * kv.x + q[4*c+1] * kv.y
                     + q[4*c+2] * kv.z + q[4*c+3] * kv.w;
            }
            s[kk] = sum;
        }

        float cm = s[0];
#pragma unroll
        for (int kk = 1; kk < 32; kk++) cm = fmaxf(cm, s[kk]);
        float mn = fmaxf(m, cm);
        float alpha = __expf(m - mn);
        lsum *= alpha;
#pragma unroll
        for (int d = 0; d < HDn; d++) acc[d] *= alpha;

#pragma unroll
        for (int kk = 0; kk < 32; kk++) {
            float p = __expf(s[kk] - mn);
            lsum += p;
#pragma unroll
            for (int c = 0; c < 8; c++) {
                float4 vv = *(const float4*)&Vs[kk][c << 2];
                acc[4*c]   += p * vv.x;
                acc[4*c+1] += p * vv.y;
                acc[4*c+2] += p * vv.z;
                acc[4*c+3] += p * vv.w;
            }
        }
        m = mn;
    }

    float inv = 1.0f / lsum;
    size_t op = ((size_t)(b * Kn + qi)) * Dn + h * HDn;
#pragma unroll
    for (int d = 0; d < HDn; d += 2) {
        float v0 = acc[d] * inv, v1 = acc[d + 1] * inv;
        __nv_bfloat16 h0, l0, h1, l1;
        split_bf16(v0, h0, l0);
        split_bf16(v1, h1, l1);
        *(__nv_bfloat162*)(Oh + op + d) = __halves2bfloat162(h0, h1);
        *(__nv_bfloat162*)(Ol + op + d) = __halves2bfloat162(l0, l1);
    }
}

// ---------------------------------------------------------------------------
// LayerNorm kernels
// ---------------------------------------------------------------------------
__device__ __forceinline__ void block_stats(float v, int t, float& mu, float& rstd)
{
    __shared__ float s1[8], s2[8];
    float su = v, sq = v * v;
#pragma unroll
    for (int o = 16; o; o >>= 1) {
        su += __shfl_down_sync(0xffffffffu, su, o);
        sq += __shfl_down_sync(0xffffffffu, sq, o);
    }
    if ((t & 31) == 0) { s1[t >> 5] = su; s2[t >> 5] = sq; }
    __syncthreads();
    float tsu = 0.0f, tsq = 0.0f;
#pragma unroll
    for (int w = 0; w < 8; w++) { tsu += s1[w]; tsq += s2[w]; }
    mu = tsu * (1.0f / Dn);
    float var = tsq * (1.0f / Dn) - mu * mu;
    rstd = rsqrtf(var + 1e-5f);
}

// ln_add: x = LN(tgt + o); writes x fp32 + bf16 hi/lo
__global__ __launch_bounds__(256) void ln_add_kernel(
    const float* __restrict__ a, const float* __restrict__ b2,
    const float* __restrict__ gam, const float* __restrict__ bet,
    float* __restrict__ xo,
    __nv_bfloat16* __restrict__ xh, __nv_bfloat16* __restrict__ xl)
{
    int row = blockIdx.x, t = threadIdx.x;
    size_t i = (size_t)row * Dn + t;
    float v = a[i] + b2[i];
    float mu, rs;
    block_stats(v, t, mu, rs);
    float r = (v - mu) * rs * gam[t] + bet[t];
    xo[i] = r;
    __nv_bfloat16 h, lo; split_bf16(r, h, lo);
    xh[i] = h; xl[i] = lo;
}

__global__ __launch_bounds__(256) void ln2_scatter_kernel(
    const float* __restrict__ a, const float* __restrict__ b2,
    const float* __restrict__ gam, const float* __restrict__ bet,
    float* __restrict__ out, const int* __restrict__ il,
    const int* __restrict__ fnum)
{
    int row = blockIdx.x, t = threadIdx.x;
    int b = row >> 10, j = row & 1023;
    size_t i = (size_t)row * Dn + t;
    float v = a[i] + b2[i];
    float mu, rs;
    block_stats(v, t, mu, rs);
    if (j < fnum[b]) {
        int idx = il[row];
        out[((size_t)b * NN + idx) * Dn + t] = (v - mu) * rs * gam[t] + bet[t];
    }
}

// ---------------------------------------------------------------------------
// Host-side orchestration
// ---------------------------------------------------------------------------
extern "C" void kernel_launch(void* const* d_in, const int* in_sizes, int n_in,
                              void* d_out, int out_size)
{
    int qp_idx = (in_sizes[1] == 8) ? 4 : 1;

    const float* query = (const float*)d_in[0];
    const float* qpos  = (const float*)d_in[qp_idx];
    const float* fgs   = (const float*)d_in[6];
    const int*   fnum  = (const int*)d_in[7];
    const int*   inds  = (const int*)d_in[8];
    const float* Wq = (const float*)d_in[9],  *bq = (const float*)d_in[10];
    const float* Wk = (const float*)d_in[11], *bk = (const float*)d_in[12];
    const float* Wv = (const float*)d_in[13], *bv = (const float*)d_in[14];
    const float* Wo = (const float*)d_in[15], *bo = (const float*)d_in[16];
    const float* g1 = (const float*)d_in[17], *be1 = (const float*)d_in[18];
    const float* W1 = (const float*)d_in[19], *b1 = (const float*)d_in[20];
    const float* W2 = (const float*)d_in[21], *b2 = (const float*)d_in[22];
    const float* g2 = (const float*)d_in[23], *be2 = (const float*)d_in[24];
    const float* Wcls = (const float*)d_in[25], *bcls = (const float*)d_in[26];

    float* out = (float*)d_out;

    unsigned char* base = nullptr;
    cudaGetSymbolAddress((void**)&base, g_mem);
#define FP(off)  ((float*)(base + (off)))
#define BF(off)  ((__nv_bfloat16*)(base + (off)))

    float *tgt = FP(OF_TGT), *Qb = FP(OF_QB), *Kb = FP(OF_KB), *Vb = FP(OF_VB);
    float *Xb = FP(OF_XB), *Yb = FP(OF_YB);
    __nv_bfloat16 *qkh = BF(OF_QKH), *qkl = BF(OF_QKL);
    __nv_bfloat16 *tgh = BF(OF_TGH), *tgl = BF(OF_TGL);
    __nv_bfloat16 *ath = BF(OF_ATH), *atl = BF(OF_ATL);
    __nv_bfloat16 *xh  = BF(OF_XH),  *xl  = BF(OF_XL);
    __nv_bfloat16 *hh  = BF(OF_HH),  *hl  = BF(OF_HL);
    __nv_bfloat16 *wqh = BF(OF_WQH), *wql = BF(OF_WQL);
    __nv_bfloat16 *wkh = BF(OF_WKH), *wkl = BF(OF_WKL);
    __nv_bfloat16 *wvh = BF(OF_WVH), *wvl = BF(OF_WVL);
    __nv_bfloat16 *woh = BF(OF_WOH), *wol = BF(OF_WOL);
    __nv_bfloat16 *w1h = BF(OF_W1H), *w1l = BF(OF_W1L);
    __nv_bfloat16 *w2h = BF(OF_W2H), *w2l = BF(OF_W2L);

    cudaFuncSetAttribute(gemm2, cudaFuncAttributeMaxDynamicSharedMemorySize, G2_SMEM);

    // ---- weight prep (transpose + bf16 split), once per launch ----
    wprep<<<dim3(8, 8, L_LAYERS), 256>>>(Wq, wqh, wql, Dn, Dn);
    wprep<<<dim3(8, 8, L_LAYERS), 256>>>(Wk, wkh, wkl, Dn, Dn);
    wprep<<<dim3(8, 8, L_LAYERS), 256>>>(Wv, wvh, wvl, Dn, Dn);
    wprep<<<dim3(8, 8, L_LAYERS), 256>>>(Wo, woh, wol, Dn, Dn);
    wprep<<<dim3(8, 32, L_LAYERS), 256>>>(W1, w1h, w1l, Dn, FFNn);
    wprep<<<dim3(32, 8, L_LAYERS), 256>>>(W2, w2h, w2l, FFNn, Dn);

    cudaMemcpyAsync(out, query, sizeof(float) * (size_t)Bn * NN * Dn,
                    cudaMemcpyDeviceToDevice);

    for (int l = 0; l < L_LAYERS; l++) {
        const int* il = inds + (size_t)l * ROWS;
        const size_t wd = (size_t)l * Dn * Dn;
        const size_t wf = (size_t)l * Dn * FFNn;

        gather_cls_kernel<<<ROWS, 256>>>(out, qpos, fgs, il, Wcls, bcls,
                                         tgt, tgh, tgl, qkh, qkl);

        // QKV batched (z = 0,1,2)
        {
            GemmP p{};
            p.Ah[0] = qkh; p.Al[0] = qkl; p.Wh[0] = wqh + wd; p.Wl[0] = wql + wd;
            p.bias[0] = bq + l * Dn; p.C[0] = Qb;
            p.Ah[1] = qkh; p.Al[1] = qkl; p.Wh[1] = wkh + wd; p.Wl[1] = wkl + wd;
            p.bias[1] = bk + l * Dn; p.C[1] = Kb;
            p.Ah[2] = tgh; p.Al[2] = tgl; p.Wh[2] = wvh + wd; p.Wl[2] = wvl + wd;
            p.bias[2] = bv + l * Dn; p.C[2] = Vb;
            gemm2<<<dim3(2, 64, 3), 128, G2_SMEM>>>(p, Dn, Dn, 0);
        }

        attn_kernel<<<dim3(Bn * Hn, Kn / 128), 128>>>(Qb, Kb, Vb, ath, atl);

        // O projection
        {
            GemmP p{};
            p.Ah[0] = ath; p.Al[0] = atl; p.Wh[0] = woh + wd; p.Wl[0] = wol + wd;
            p.bias[0] = bo + l * Dn; p.C[0] = Yb;
            gemm2<<<dim3(2, 64, 1), 128, G2_SMEM>>>(p, Dn, Dn, 0);
        }

        ln_add_kernel<<<ROWS, 256>>>(tgt, Yb, g1 + l * Dn, be1 + l * Dn, Xb, xh, xl);

        // FFN1 (relu, bf16 split out)
        {
            GemmP p{};
            p.Ah[0] = xh; p.Al[0] = xl; p.Wh[0] = w1h + wf; p.Wl[0] = w1l + wf;
            p.bias[0] = b1 + l * FFNn; p.Ch[0] = hh; p.Cl[0] = hl;
            gemm2<<<dim3(8, 64, 1), 128, G2_SMEM>>>(p, FFNn, Dn, 2);
        }
        // FFN2
        {
            GemmP p{};
            p.Ah[0] = hh; p.Al[0] = hl; p.Wh[0] = w2h + wf; p.Wl[0] = w2l + wf;
            p.bias[0] = b2 + l * Dn; p.C[0] = Yb;
            gemm2<<<dim3(2, 64, 1), 128, G2_SMEM>>>(p, Dn, FFNn, 0);
        }

        ln2_scatter_kernel<<<ROWS, 256>>>(Xb, Yb, g2 + l * Dn, be2 + l * Dn,
                                          out, il, fnum);
    }
}

// round 6
// speedup vs baseline: 2.5387x; 1.7768x over previous
#include <cuda_runtime.h>
#include <cuda_bf16.h>
#include <cstdint>

// ---------------------------------------------------------------------------
// Focus-DETR encoder — round 6: round-5 design with the bf16x2 bit-cast fixed.
// Tensor-core flash attention (bf16x3 split), head-layout QKV epilogue,
// cheap gather reduction.
// ---------------------------------------------------------------------------

#define L_LAYERS 6
#define Bn 4
#define NN 23890
#define Kn 1024
#define Dn 256
#define Hn 8
#define HDn 32
#define FFNn 1024
#define NCLSn 15

#define ROWS (Bn * Kn)          // 4096
#define RD   (ROWS * Dn)        // 1048576 elements

// ---------------- scratch carving ----------------
constexpr size_t SZ_F  = (size_t)RD * 4;
constexpr size_t SZ_B  = (size_t)RD * 2;
constexpr size_t SZ_H  = (size_t)ROWS * FFNn * 2;
constexpr size_t SZ_WD = (size_t)L_LAYERS * Dn * Dn * 2;
constexpr size_t SZ_W1 = (size_t)L_LAYERS * Dn * FFNn * 2;

constexpr size_t OF_TGT = 0;
constexpr size_t OF_XB  = OF_TGT + SZ_F;
constexpr size_t OF_YB  = OF_XB  + SZ_F;
constexpr size_t OF_QKH = OF_YB  + SZ_F;
constexpr size_t OF_QKL = OF_QKH + SZ_B;
constexpr size_t OF_TGH = OF_QKL + SZ_B;
constexpr size_t OF_TGL = OF_TGH + SZ_B;
constexpr size_t OF_QH  = OF_TGL + SZ_B;
constexpr size_t OF_QL  = OF_QH  + SZ_B;
constexpr size_t OF_KH  = OF_QL  + SZ_B;
constexpr size_t OF_KL  = OF_KH  + SZ_B;
constexpr size_t OF_VH  = OF_KL  + SZ_B;
constexpr size_t OF_VL  = OF_VH  + SZ_B;
constexpr size_t OF_ATH = OF_VL  + SZ_B;
constexpr size_t OF_ATL = OF_ATH + SZ_B;
constexpr size_t OF_XH  = OF_ATL + SZ_B;
constexpr size_t OF_XL  = OF_XH  + SZ_B;
constexpr size_t OF_HH  = OF_XL  + SZ_B;
constexpr size_t OF_HL  = OF_HH  + SZ_H;
constexpr size_t OF_WQH = OF_HL  + SZ_H;
constexpr size_t OF_WQL = OF_WQH + SZ_WD;
constexpr size_t OF_WKH = OF_WQL + SZ_WD;
constexpr size_t OF_WKL = OF_WKH + SZ_WD;
constexpr size_t OF_WVH = OF_WKL + SZ_WD;
constexpr size_t OF_WVL = OF_WVH + SZ_WD;
constexpr size_t OF_WOH = OF_WVL + SZ_WD;
constexpr size_t OF_WOL = OF_WOH + SZ_WD;
constexpr size_t OF_W1H = OF_WOL + SZ_WD;
constexpr size_t OF_W1L = OF_W1H + SZ_W1;
constexpr size_t OF_W2H = OF_W1L + SZ_W1;
constexpr size_t OF_W2L = OF_W2H + SZ_W1;
constexpr size_t G_TOTAL = OF_W2L + SZ_W1;

__device__ __align__(1024) unsigned char g_mem[G_TOTAL];

// ============================ PTX helpers ==================================

__device__ __forceinline__ uint32_t smem_u32(const void* p) {
    uint32_t a;
    asm("{ .reg .u64 t; cvta.to.shared.u64 t, %1; cvt.u32.u64 %0, t; }"
        : "=r"(a) : "l"(p));
    return a;
}

#define CP16(sa, ga)                                                            \
    asm volatile("cp.async.ca.shared.global [%0], [%1], 16;"                    \
                 :: "r"(sa), "l"(__cvta_generic_to_global(ga)))
#define CP_COMMIT() asm volatile("cp.async.commit_group;" ::: "memory")
#define CP_WAIT0()  asm volatile("cp.async.wait_group 0;" ::: "memory")
#define CP_WAIT1()  asm volatile("cp.async.wait_group 1;" ::: "memory")

#define LDSM4(r, addr)                                                          \
    asm volatile("ldmatrix.sync.aligned.m8n8.x4.shared.b16 {%0,%1,%2,%3}, [%4];"\
        : "=r"((r)[0]), "=r"((r)[1]), "=r"((r)[2]), "=r"((r)[3]) : "r"(addr))

#define MMA_BF16(d, a, b0, b1)                                                  \
    asm volatile("mma.sync.aligned.m16n8k16.row.col.f32.bf16.bf16.f32 "         \
        "{%0,%1,%2,%3}, {%4,%5,%6,%7}, {%8,%9}, {%0,%1,%2,%3};"                 \
        : "+f"((d)[0]), "+f"((d)[1]), "+f"((d)[2]), "+f"((d)[3])                \
        : "r"((a)[0]), "r"((a)[1]), "r"((a)[2]), "r"((a)[3]), "r"(b0), "r"(b1))

__device__ __forceinline__ void split_bf16(float v, __nv_bfloat16& h, __nv_bfloat16& l) {
    h = __float2bfloat16(v);
    l = __float2bfloat16(v - __bfloat162float(h));
}

__device__ __forceinline__ uint32_t bf2_u32(__nv_bfloat16 a, __nv_bfloat16 b) {
    union { __nv_bfloat162 v; uint32_t u; } cvt;
    cvt.v = __halves2bfloat162(a, b);
    return cvt.u;
}

// split a pair of floats into packed hi/lo bf16x2 words
__device__ __forceinline__ void split2_pack(float v0, float v1,
                                            uint32_t& hi, uint32_t& lo) {
    __nv_bfloat16 h0, l0, h1, l1;
    split_bf16(v0, h0, l0);
    split_bf16(v1, h1, l1);
    hi = bf2_u32(h0, h1);
    lo = bf2_u32(l0, l1);
}

__device__ __forceinline__ float ex2(float x) {
    float r;
    asm("ex2.approx.ftz.f32 %0, %1;" : "=f"(r) : "f"(x));
    return r;
}

// ===================== weight prep: transpose + split ======================
__global__ __launch_bounds__(256) void wprep(
    const float* __restrict__ W, __nv_bfloat16* __restrict__ Wh,
    __nv_bfloat16* __restrict__ Wl, int Kd, int Ncols)
{
    __shared__ float tile[32][33];
    const int l  = blockIdx.z;
    const int k0 = blockIdx.x << 5, n0 = blockIdx.y << 5;
    const int tx = threadIdx.x & 31, ty = threadIdx.x >> 5;

    const float* Wp = W + (size_t)l * Kd * Ncols;
#pragma unroll
    for (int r = ty; r < 32; r += 8)
        tile[r][tx] = Wp[(size_t)(k0 + r) * Ncols + n0 + tx];
    __syncthreads();

    __nv_bfloat16* Hp = Wh + ((size_t)l * Ncols + n0) * Kd + k0;
    __nv_bfloat16* Lp = Wl + ((size_t)l * Ncols + n0) * Kd + k0;
#pragma unroll
    for (int r = ty; r < 32; r += 8) {
        float v = tile[tx][r];
        __nv_bfloat16 h, lo; split_bf16(v, h, lo);
        Hp[(size_t)r * Kd + tx] = h;
        Lp[(size_t)r * Kd + tx] = lo;
    }
}

// ============================ bf16x3 GEMM ==================================
struct GemmP {
    const __nv_bfloat16 *Ah[3], *Al[3], *Wh[3], *Wl[3];
    const float* bias[3];
    float* C[3];
    __nv_bfloat16 *Ch[3], *Cl[3];
};

#define G2_AH 0
#define G2_AL 5120
#define G2_BH 10240
#define G2_BL 20480
#define G2_BUF 30720
#define G2_SMEM (2 * G2_BUF)

__global__ __launch_bounds__(128) void gemm2(GemmP p, int Ncols, int Kd, int mode)
{
    extern __shared__ __align__(16) char smem[];
    const uint32_t sb = smem_u32(smem);

    const int z    = blockIdx.z;
    const __nv_bfloat16* Ah = p.Ah[z];
    const __nv_bfloat16* Al = p.Al[z];
    const __nv_bfloat16* Wh = p.Wh[z];
    const __nv_bfloat16* Wl = p.Wl[z];

    const int tid  = threadIdx.x;
    const int lane = tid & 31;
    const int wn   = tid >> 5;
    const int bm   = blockIdx.y << 6;
    const int bn   = blockIdx.x << 7;

    float acc[4][4][4];
#pragma unroll
    for (int i = 0; i < 4; i++)
#pragma unroll
        for (int j = 0; j < 4; j++)
#pragma unroll
            for (int q = 0; q < 4; q++) acc[i][j][q] = 0.0f;

    const int a_r = lane & 15;
    const int a_c = (lane >> 4) << 3;
    const int b_r = wn * 32 + (lane & 7) + ((lane >> 4) << 3);
    const int b_c = ((lane >> 3) & 1) << 3;

    const int nc = Kd >> 5;

    auto issue = [&](int c, int buf) {
        const uint32_t sa = sb + buf * G2_BUF;
        const size_t kb = (size_t)(c << 5) * 2;
#pragma unroll
        for (int i = 0; i < 2; i++) {
            int s = tid + (i << 7);
            int row = s >> 2, seg = s & 3;
            size_t go = ((size_t)(bm + row) * Kd) * 2 + kb + seg * 16;
            uint32_t so = sa + row * 80 + seg * 16;
            CP16(so + G2_AH, (const char*)Ah + go);
            CP16(so + G2_AL, (const char*)Al + go);
        }
#pragma unroll
        for (int i = 0; i < 4; i++) {
            int s = tid + (i << 7);
            int row = s >> 2, seg = s & 3;
            size_t go = ((size_t)(bn + row) * Kd) * 2 + kb + seg * 16;
            uint32_t so = sa + row * 80 + seg * 16;
            CP16(so + G2_BH, (const char*)Wh + go);
            CP16(so + G2_BL, (const char*)Wl + go);
        }
        CP_COMMIT();
    };

    issue(0, 0);

    for (int c = 0; c < nc; c++) {
        const int buf = c & 1;
        if (c + 1 < nc) { issue(c + 1, buf ^ 1); CP_WAIT1(); }
        else           { CP_WAIT0(); }
        __syncthreads();

        const uint32_t sa = sb + buf * G2_BUF;
#pragma unroll
        for (int ks = 0; ks < 2; ks++) {
            uint32_t ah[4][4], al[4][4];
#pragma unroll
            for (int mb = 0; mb < 4; mb++) {
                uint32_t ao = sa + (uint32_t)(a_r + mb * 16) * 80 + (ks * 16 + a_c) * 2;
                LDSM4(ah[mb], ao + G2_AH);
                LDSM4(al[mb], ao + G2_AL);
            }
            uint32_t bh[2][4], bl[2][4];
#pragma unroll
            for (int np = 0; np < 2; np++) {
                uint32_t bo = sa + (uint32_t)(b_r + np * 16) * 80 + (ks * 16 + b_c) * 2;
                LDSM4(bh[np], bo + G2_BH);
                LDSM4(bl[np], bo + G2_BL);
            }
#pragma unroll
            for (int mb = 0; mb < 4; mb++)
#pragma unroll
                for (int nb = 0; nb < 4; nb++) {
                    const int np = nb >> 1, sl = (nb & 1) << 1;
                    MMA_BF16(acc[mb][nb], ah[mb], bh[np][sl], bh[np][sl + 1]);
                    MMA_BF16(acc[mb][nb], al[mb], bh[np][sl], bh[np][sl + 1]);
                    MMA_BF16(acc[mb][nb], ah[mb], bl[np][sl], bl[np][sl + 1]);
                }
        }
        __syncthreads();
    }

    const float* bias = p.bias[z];
    const int r0 = bm + (lane >> 2);
    const int c0 = bn + wn * 32 + ((lane & 3) << 1);

    if (mode == 0) {
        float* C = p.C[z];
#pragma unroll
        for (int mb = 0; mb < 4; mb++)
#pragma unroll
            for (int nb = 0; nb < 4; nb++) {
                int rr = r0 + mb * 16, cc = c0 + nb * 8;
                float bb0 = bias[cc], bb1 = bias[cc + 1];
                float2 v0, v1;
                v0.x = acc[mb][nb][0] + bb0; v0.y = acc[mb][nb][1] + bb1;
                v1.x = acc[mb][nb][2] + bb0; v1.y = acc[mb][nb][3] + bb1;
                *(float2*)(C + (size_t)rr * Ncols + cc)       = v0;
                *(float2*)(C + (size_t)(rr + 8) * Ncols + cc) = v1;
            }
    } else if (mode == 2) {
        __nv_bfloat16* Ch = p.Ch[z];
        __nv_bfloat16* Cl = p.Cl[z];
#pragma unroll
        for (int mb = 0; mb < 4; mb++)
#pragma unroll
            for (int nb = 0; nb < 4; nb++) {
                int rr = r0 + mb * 16, cc = c0 + nb * 8;
                float bb0 = bias[cc], bb1 = bias[cc + 1];
#pragma unroll
                for (int hrow = 0; hrow < 2; hrow++) {
                    int r = rr + hrow * 8;
                    float v0 = fmaxf(acc[mb][nb][2 * hrow]     + bb0, 0.0f);
                    float v1 = fmaxf(acc[mb][nb][2 * hrow + 1] + bb1, 0.0f);
                    uint32_t hw, lw;
                    split2_pack(v0, v1, hw, lw);
                    *(uint32_t*)(Ch + (size_t)r * Ncols + cc) = hw;
                    *(uint32_t*)(Cl + (size_t)r * Ncols + cc) = lw;
                }
            }
    } else {    // mode 3: attention QKV layout
        __nv_bfloat16* Ch = p.Ch[z];
        __nv_bfloat16* Cl = p.Cl[z];
#pragma unroll
        for (int mb = 0; mb < 4; mb++)
#pragma unroll
            for (int nb = 0; nb < 4; nb++) {
                int rr = r0 + mb * 16, cc = c0 + nb * 8;
                float bb0 = bias[cc], bb1 = bias[cc + 1];
                int bh = ((rr >> 10) << 3) + (cc >> 5);
                int d  = cc & 31;
#pragma unroll
                for (int hrow = 0; hrow < 2; hrow++) {
                    int r = rr + hrow * 8;
                    int q = r & 1023;
                    float v0 = acc[mb][nb][2 * hrow]     + bb0;
                    float v1 = acc[mb][nb][2 * hrow + 1] + bb1;
                    __nv_bfloat16 h0, l0, h1, l1;
                    split_bf16(v0, h0, l0);
                    split_bf16(v1, h1, l1);
                    if (z < 2) {
                        size_t a = ((size_t)bh * 1024 + q) * 32 + d;
                        *(uint32_t*)(Ch + a) = bf2_u32(h0, h1);
                        *(uint32_t*)(Cl + a) = bf2_u32(l0, l1);
                    } else {
                        size_t a = ((size_t)bh * 32 + d) * 1024 + q;
                        Ch[a] = h0; Ch[a + 1024] = h1;
                        Cl[a] = l0; Cl[a + 1024] = l1;
                    }
                }
            }
    }
}

// ====================== tensor-core flash attention ========================
#define AT_QH 0
#define AT_QL 10240
#define AT_K  20480             // + buf*10240 : Kh(5120) Kl(5120)
#define AT_V  40960             // + buf*9216  : Vh(4608) Vl(4608)
#define AT_SMEM 59392
#define BETA 0.2550165213f      // log2(e)/sqrt(32)

__global__ __launch_bounds__(128) void attn_tc(
    const __nv_bfloat16* __restrict__ Qh, const __nv_bfloat16* __restrict__ Ql,
    const __nv_bfloat16* __restrict__ Kh, const __nv_bfloat16* __restrict__ Kl,
    const __nv_bfloat16* __restrict__ Vh, const __nv_bfloat16* __restrict__ Vl,
    __nv_bfloat16* __restrict__ Oh, __nv_bfloat16* __restrict__ Ol)
{
    extern __shared__ __align__(16) char smem[];
    const uint32_t sb = smem_u32(smem);

    const int tid  = threadIdx.x;
    const int lane = tid & 31;
    const int warp = tid >> 5;
    const int bh   = blockIdx.x;
    const int q0   = blockIdx.y << 7;

    // ---- Q stage (one-time) ----
    {
        const char* gqh = (const char*)(Qh + ((size_t)bh * 1024 + q0) * 32);
        const char* gql = (const char*)(Ql + ((size_t)bh * 1024 + q0) * 32);
#pragma unroll
        for (int i = 0; i < 4; i++) {
            int s = tid + (i << 7);
            int row = s >> 2, seg = s & 3;
            size_t go = (size_t)row * 64 + seg * 16;
            uint32_t so = (uint32_t)row * 80 + seg * 16;
            CP16(sb + AT_QH + so, gqh + go);
            CP16(sb + AT_QL + so, gql + go);
        }
    }

    auto issueKV = [&](int c, int buf) {
        const int kc = c << 6;
        const uint32_t sk = sb + AT_K + buf * 10240;
        const uint32_t sv = sb + AT_V + buf * 9216;
        const char* gkh = (const char*)(Kh + ((size_t)bh * 1024 + kc) * 32);
        const char* gkl = (const char*)(Kl + ((size_t)bh * 1024 + kc) * 32);
#pragma unroll
        for (int i = 0; i < 2; i++) {
            int s = tid + (i << 7);
            int row = s >> 2, seg = s & 3;
            size_t go = (size_t)row * 64 + seg * 16;
            uint32_t so = (uint32_t)row * 80 + seg * 16;
            CP16(sk + so, gkh + go);
            CP16(sk + 5120 + so, gkl + go);
        }
        const char* gvh = (const char*)(Vh + (size_t)bh * 32 * 1024 + kc);
        const char* gvl = (const char*)(Vl + (size_t)bh * 32 * 1024 + kc);
#pragma unroll
        for (int i = 0; i < 2; i++) {
            int s = tid + (i << 7);
            int d = s >> 3, seg = s & 7;
            size_t go = (size_t)d * 2048 + seg * 16;
            uint32_t so = (uint32_t)d * 144 + seg * 16;
            CP16(sv + so, gvh + go);
            CP16(sv + 4608 + so, gvl + go);
        }
        CP_COMMIT();
    };

    issueKV(0, 0);

    float o[2][4][4];
    float m[2][2], l[2][2];
#pragma unroll
    for (int a = 0; a < 2; a++)
#pragma unroll
        for (int b = 0; b < 4; b++)
#pragma unroll
            for (int q = 0; q < 4; q++) o[a][b][q] = 0.0f;
#pragma unroll
    for (int a = 0; a < 2; a++) { m[a][0] = m[a][1] = -1e30f; l[a][0] = l[a][1] = 0.0f; }

    uint32_t qfh[2][2][4], qfl[2][2][4];

    const int a_r = lane & 15;
    const int a_c = (lane >> 4) << 3;
    const int b_rr = (lane & 7) + ((lane >> 4) << 3);
    const int b_cc = ((lane >> 3) & 1) << 3;

    for (int c = 0; c < 16; c++) {
        const int buf = c & 1;
        if (c + 1 < 16) { issueKV(c + 1, buf ^ 1); CP_WAIT1(); }
        else            { CP_WAIT0(); }
        __syncthreads();

        if (c == 0) {
#pragma unroll
            for (int mb = 0; mb < 2; mb++)
#pragma unroll
                for (int kk = 0; kk < 2; kk++) {
                    uint32_t ao = (uint32_t)(warp * 32 + mb * 16 + a_r) * 80
                                + (kk * 16 + a_c) * 2;
                    LDSM4(qfh[mb][kk], sb + AT_QH + ao);
                    LDSM4(qfl[mb][kk], sb + AT_QL + ao);
                }
        }

        const uint32_t sk = sb + AT_K + buf * 10240;
        const uint32_t sv = sb + AT_V + buf * 9216;

        // ---- S = Q K^T ----
        float s[2][8][4];
#pragma unroll
        for (int a = 0; a < 2; a++)
#pragma unroll
            for (int b = 0; b < 8; b++)
#pragma unroll
                for (int q = 0; q < 4; q++) s[a][b][q] = 0.0f;

#pragma unroll
        for (int g = 0; g < 4; g++) {
            uint32_t kfh[2][4], kfl[2][4];
#pragma unroll
            for (int kk = 0; kk < 2; kk++) {
                uint32_t bo = (uint32_t)(g * 16 + b_rr) * 80 + (kk * 16 + b_cc) * 2;
                LDSM4(kfh[kk], sk + bo);
                LDSM4(kfl[kk], sk + 5120 + bo);
            }
#pragma unroll
            for (int mb = 0; mb < 2; mb++)
#pragma unroll
                for (int nb = 0; nb < 2; nb++) {
                    const int nt = g * 2 + nb, sl = nb << 1;
#pragma unroll
                    for (int kk = 0; kk < 2; kk++) {
                        MMA_BF16(s[mb][nt], qfh[mb][kk], kfh[kk][sl], kfh[kk][sl + 1]);
                        MMA_BF16(s[mb][nt], qfl[mb][kk], kfh[kk][sl], kfh[kk][sl + 1]);
                        MMA_BF16(s[mb][nt], qfh[mb][kk], kfl[kk][sl], kfl[kk][sl + 1]);
                    }
                }
        }

        // ---- online softmax ----
        float alpha[2][2], mb_new[2][2];
#pragma unroll
        for (int mb = 0; mb < 2; mb++) {
#pragma unroll
            for (int h = 0; h < 2; h++) {
                float mx = -1e30f;
#pragma unroll
                for (int nt = 0; nt < 8; nt++) {
                    mx = fmaxf(mx, s[mb][nt][2 * h]);
                    mx = fmaxf(mx, s[mb][nt][2 * h + 1]);
                }
                mx = fmaxf(mx, __shfl_xor_sync(0xffffffffu, mx, 1));
                mx = fmaxf(mx, __shfl_xor_sync(0xffffffffu, mx, 2));
                float mn = fmaxf(m[mb][h], mx);
                alpha[mb][h] = ex2((m[mb][h] - mn) * BETA);
                mb_new[mb][h] = mn;
                m[mb][h] = mn;
            }
        }
#pragma unroll
        for (int mb = 0; mb < 2; mb++) {
            float nm0 = mb_new[mb][0] * BETA, nm1 = mb_new[mb][1] * BETA;
#pragma unroll
            for (int nt = 0; nt < 8; nt++) {
                s[mb][nt][0] = ex2(fmaf(s[mb][nt][0], BETA, -nm0));
                s[mb][nt][1] = ex2(fmaf(s[mb][nt][1], BETA, -nm0));
                s[mb][nt][2] = ex2(fmaf(s[mb][nt][2], BETA, -nm1));
                s[mb][nt][3] = ex2(fmaf(s[mb][nt][3], BETA, -nm1));
            }
        }
#pragma unroll
        for (int mb = 0; mb < 2; mb++) {
#pragma unroll
            for (int h = 0; h < 2; h++) {
                float su = 0.0f;
#pragma unroll
                for (int nt = 0; nt < 8; nt++)
                    su += s[mb][nt][2 * h] + s[mb][nt][2 * h + 1];
                su += __shfl_xor_sync(0xffffffffu, su, 1);
                su += __shfl_xor_sync(0xffffffffu, su, 2);
                l[mb][h] = l[mb][h] * alpha[mb][h] + su;
            }
#pragma unroll
            for (int nb = 0; nb < 4; nb++) {
                o[mb][nb][0] *= alpha[mb][0];
                o[mb][nb][1] *= alpha[mb][0];
                o[mb][nb][2] *= alpha[mb][1];
                o[mb][nb][3] *= alpha[mb][1];
            }
        }

        // ---- O += P V ----
#pragma unroll
        for (int kt = 0; kt < 4; kt++) {
            uint32_t vfh[2][4], vfl[2][4];
#pragma unroll
            for (int g = 0; g < 2; g++) {
                uint32_t bo = (uint32_t)(g * 16 + b_rr) * 144 + (kt * 16 + b_cc) * 2;
                LDSM4(vfh[g], sv + bo);
                LDSM4(vfl[g], sv + 4608 + bo);
            }
#pragma unroll
            for (int mb = 0; mb < 2; mb++) {
                const int t0 = kt * 2, t1 = kt * 2 + 1;
                uint32_t ph[4], pl[4];
                split2_pack(s[mb][t0][0], s[mb][t0][1], ph[0], pl[0]);
                split2_pack(s[mb][t0][2], s[mb][t0][3], ph[1], pl[1]);
                split2_pack(s[mb][t1][0], s[mb][t1][1], ph[2], pl[2]);
                split2_pack(s[mb][t1][2], s[mb][t1][3], ph[3], pl[3]);
#pragma unroll
                for (int nb = 0; nb < 4; nb++) {
                    const int g = nb >> 1, sl = (nb & 1) << 1;
                    MMA_BF16(o[mb][nb], ph, vfh[g][sl], vfh[g][sl + 1]);
                    MMA_BF16(o[mb][nb], pl, vfh[g][sl], vfh[g][sl + 1]);
                    MMA_BF16(o[mb][nb], ph, vfl[g][sl], vfl[g][sl + 1]);
                }
            }
        }
        __syncthreads();
    }

    // ---- epilogue ----
    const int b  = bh >> 3;
    const int hh = bh & 7;
#pragma unroll
    for (int mb = 0; mb < 2; mb++) {
        float i0 = 1.0f / l[mb][0], i1 = 1.0f / l[mb][1];
#pragma unroll
        for (int h = 0; h < 2; h++) {
            int row = b * 1024 + q0 + warp * 32 + mb * 16 + h * 8 + (lane >> 2);
            float inv = h ? i1 : i0;
#pragma unroll
            for (int nb = 0; nb < 4; nb++) {
                int d = nb * 8 + ((lane & 3) << 1);
                float v0 = o[mb][nb][2 * h]     * inv;
                float v1 = o[mb][nb][2 * h + 1] * inv;
                uint32_t hw, lw;
                split2_pack(v0, v1, hw, lw);
                size_t a = (size_t)row * Dn + hh * 32 + d;
                *(uint32_t*)(Oh + a) = hw;
                *(uint32_t*)(Ol + a) = lw;
            }
        }
    }
}

// ---------------------------------------------------------------------------
// Gather + MCSP (cheap reduction)
// ---------------------------------------------------------------------------
__global__ __launch_bounds__(256) void gather_cls_kernel(
    const float* __restrict__ out, const float* __restrict__ qpos,
    const float* __restrict__ fgs, const int* __restrict__ il,
    const float* __restrict__ Wcls, const float* __restrict__ bcls,
    float* __restrict__ tgt,
    __nv_bfloat16* __restrict__ tgh, __nv_bfloat16* __restrict__ tgl,
    __nv_bfloat16* __restrict__ qkh, __nv_bfloat16* __restrict__ qkl)
{
    __shared__ float qs[Dn];
    __shared__ float sc[16];

    int row = blockIdx.x;
    int b   = row >> 10;
    int t   = threadIdx.x;
    int lane = t & 31, w = t >> 5;
    int idx = il[row];
    size_t src = ((size_t)b * NN + idx) * Dn + t;
    float qv = out[src];
    qs[t] = qv;
    __syncthreads();

#pragma unroll
    for (int ci = 0; ci < 2; ci++) {
        int c = w + ci * 8;
        if (c < NCLSn) {
            float sum = 0.0f;
#pragma unroll
            for (int j = 0; j < 8; j++) {
                int e = lane + (j << 5);
                sum += qs[e] * Wcls[e * NCLSn + c];
            }
#pragma unroll
            for (int o = 16; o; o >>= 1) sum += __shfl_down_sync(0xffffffffu, sum, o);
            if (lane == 0) sc[c] = sum + bcls[c];
        }
    }
    __syncthreads();

    float mx = sc[0];
#pragma unroll
    for (int c = 1; c < NCLSn; c++) mx = fmaxf(mx, sc[c]);
    float mc = (1.0f / (1.0f + __expf(-mx))) * fgs[(size_t)b * NN + idx];

    float tv = tgt[(size_t)row * Dn + t] = qv * mc;
    float qk = tv + qpos[src];
    size_t i = (size_t)row * Dn + t;
    __nv_bfloat16 h, lo;
    split_bf16(tv, h, lo); tgh[i] = h; tgl[i] = lo;
    split_bf16(qk, h, lo); qkh[i] = h; qkl[i] = lo;
}

// ---------------------------------------------------------------------------
// LayerNorm kernels
// ---------------------------------------------------------------------------
__device__ __forceinline__ void block_stats(float v, int t, float& mu, float& rstd)
{
    __shared__ float s1[8], s2[8];
    float su = v, sq = v * v;
#pragma unroll
    for (int o = 16; o; o >>= 1) {
        su += __shfl_down_sync(0xffffffffu, su, o);
        sq += __shfl_down_sync(0xffffffffu, sq, o);
    }
    if ((t & 31) == 0) { s1[t >> 5] = su; s2[t >> 5] = sq; }
    __syncthreads();
    float tsu = 0.0f, tsq = 0.0f;
#pragma unroll
    for (int w = 0; w < 8; w++) { tsu += s1[w]; tsq += s2[w]; }
    mu = tsu * (1.0f / Dn);
    float var = tsq * (1.0f / Dn) - mu * mu;
    rstd = rsqrtf(var + 1e-5f);
}

__global__ __launch_bounds__(256) void ln_add_kernel(
    const float* __restrict__ a, const float* __restrict__ b2,
    const float* __restrict__ gam, const float* __restrict__ bet,
    float* __restrict__ xo,
    __nv_bfloat16* __restrict__ xh, __nv_bfloat16* __restrict__ xl)
{
    int row = blockIdx.x, t = threadIdx.x;
    size_t i = (size_t)row * Dn + t;
    float v = a[i] + b2[i];
    float mu, rs;
    block_stats(v, t, mu, rs);
    float r = (v - mu) * rs * gam[t] + bet[t];
    xo[i] = r;
    __nv_bfloat16 h, lo; split_bf16(r, h, lo);
    xh[i] = h; xl[i] = lo;
}

__global__ __launch_bounds__(256) void ln2_scatter_kernel(
    const float* __restrict__ a, const float* __restrict__ b2,
    const float* __restrict__ gam, const float* __restrict__ bet,
    float* __restrict__ out, const int* __restrict__ il,
    const int* __restrict__ fnum)
{
    int row = blockIdx.x, t = threadIdx.x;
    int b = row >> 10, j = row & 1023;
    size_t i = (size_t)row * Dn + t;
    float v = a[i] + b2[i];
    float mu, rs;
    block_stats(v, t, mu, rs);
    if (j < fnum[b]) {
        int idx = il[row];
        out[((size_t)b * NN + idx) * Dn + t] = (v - mu) * rs * gam[t] + bet[t];
    }
}

// ---------------------------------------------------------------------------
// Host-side orchestration
// ---------------------------------------------------------------------------
extern "C" void kernel_launch(void* const* d_in, const int* in_sizes, int n_in,
                              void* d_out, int out_size)
{
    int qp_idx = (in_sizes[1] == 8) ? 4 : 1;

    const float* query = (const float*)d_in[0];
    const float* qpos  = (const float*)d_in[qp_idx];
    const float* fgs   = (const float*)d_in[6];
    const int*   fnum  = (const int*)d_in[7];
    const int*   inds  = (const int*)d_in[8];
    const float* Wq = (const float*)d_in[9],  *bq = (const float*)d_in[10];
    const float* Wk = (const float*)d_in[11], *bk = (const float*)d_in[12];
    const float* Wv = (const float*)d_in[13], *bv = (const float*)d_in[14];
    const float* Wo = (const float*)d_in[15], *bo = (const float*)d_in[16];
    const float* g1 = (const float*)d_in[17], *be1 = (const float*)d_in[18];
    const float* W1 = (const float*)d_in[19], *b1 = (const float*)d_in[20];
    const float* W2 = (const float*)d_in[21], *b2 = (const float*)d_in[22];
    const float* g2 = (const float*)d_in[23], *be2 = (const float*)d_in[24];
    const float* Wcls = (const float*)d_in[25], *bcls = (const float*)d_in[26];

    float* out = (float*)d_out;

    unsigned char* base = nullptr;
    cudaGetSymbolAddress((void**)&base, g_mem);
#define FP(off)  ((float*)(base + (off)))
#define BF(off)  ((__nv_bfloat16*)(base + (off)))

    float *tgt = FP(OF_TGT), *Xb = FP(OF_XB), *Yb = FP(OF_YB);
    __nv_bfloat16 *qkh = BF(OF_QKH), *qkl = BF(OF_QKL);
    __nv_bfloat16 *tgh = BF(OF_TGH), *tgl = BF(OF_TGL);
    __nv_bfloat16 *qh  = BF(OF_QH),  *ql  = BF(OF_QL);
    __nv_bfloat16 *kh  = BF(OF_KH),  *kl  = BF(OF_KL);
    __nv_bfloat16 *vh  = BF(OF_VH),  *vl  = BF(OF_VL);
    __nv_bfloat16 *ath = BF(OF_ATH), *atl = BF(OF_ATL);
    __nv_bfloat16 *xh  = BF(OF_XH),  *xl  = BF(OF_XL);
    __nv_bfloat16 *hh  = BF(OF_HH),  *hl  = BF(OF_HL);
    __nv_bfloat16 *wqh = BF(OF_WQH), *wql = BF(OF_WQL);
    __nv_bfloat16 *wkh = BF(OF_WKH), *wkl = BF(OF_WKL);
    __nv_bfloat16 *wvh = BF(OF_WVH), *wvl = BF(OF_WVL);
    __nv_bfloat16 *woh = BF(OF_WOH), *wol = BF(OF_WOL);
    __nv_bfloat16 *w1h = BF(OF_W1H), *w1l = BF(OF_W1L);
    __nv_bfloat16 *w2h = BF(OF_W2H), *w2l = BF(OF_W2L);

    cudaFuncSetAttribute(gemm2, cudaFuncAttributeMaxDynamicSharedMemorySize, G2_SMEM);
    cudaFuncSetAttribute(attn_tc, cudaFuncAttributeMaxDynamicSharedMemorySize, AT_SMEM);

    wprep<<<dim3(8, 8, L_LAYERS), 256>>>(Wq, wqh, wql, Dn, Dn);
    wprep<<<dim3(8, 8, L_LAYERS), 256>>>(Wk, wkh, wkl, Dn, Dn);
    wprep<<<dim3(8, 8, L_LAYERS), 256>>>(Wv, wvh, wvl, Dn, Dn);
    wprep<<<dim3(8, 8, L_LAYERS), 256>>>(Wo, woh, wol, Dn, Dn);
    wprep<<<dim3(8, 32, L_LAYERS), 256>>>(W1, w1h, w1l, Dn, FFNn);
    wprep<<<dim3(32, 8, L_LAYERS), 256>>>(W2, w2h, w2l, FFNn, Dn);

    cudaMemcpyAsync(out, query, sizeof(float) * (size_t)Bn * NN * Dn,
                    cudaMemcpyDeviceToDevice);

    for (int l = 0; l < L_LAYERS; l++) {
        const int* il = inds + (size_t)l * ROWS;
        const size_t wd = (size_t)l * Dn * Dn;
        const size_t wf = (size_t)l * Dn * FFNn;

        gather_cls_kernel<<<ROWS, 256>>>(out, qpos, fgs, il, Wcls, bcls,
                                         tgt, tgh, tgl, qkh, qkl);

        {
            GemmP p{};
            p.Ah[0] = qkh; p.Al[0] = qkl; p.Wh[0] = wqh + wd; p.Wl[0] = wql + wd;
            p.bias[0] = bq + l * Dn; p.Ch[0] = qh; p.Cl[0] = ql;
            p.Ah[1] = qkh; p.Al[1] = qkl; p.Wh[1] = wkh + wd; p.Wl[1] = wkl + wd;
            p.bias[1] = bk + l * Dn; p.Ch[1] = kh; p.Cl[1] = kl;
            p.Ah[2] = tgh; p.Al[2] = tgl; p.Wh[2] = wvh + wd; p.Wl[2] = wvl + wd;
            p.bias[2] = bv + l * Dn; p.Ch[2] = vh; p.Cl[2] = vl;
            gemm2<<<dim3(2, 64, 3), 128, G2_SMEM>>>(p, Dn, Dn, 3);
        }

        attn_tc<<<dim3(Bn * Hn, Kn / 128), 128, AT_SMEM>>>(qh, ql, kh, kl, vh, vl,
                                                           ath, atl);

        {
            GemmP p{};
            p.Ah[0] = ath; p.Al[0] = atl; p.Wh[0] = woh + wd; p.Wl[0] = wol + wd;
            p.bias[0] = bo + l * Dn; p.C[0] = Yb;
            gemm2<<<dim3(2, 64, 1), 128, G2_SMEM>>>(p, Dn, Dn, 0);
        }

        ln_add_kernel<<<ROWS, 256>>>(tgt, Yb, g1 + l * Dn, be1 + l * Dn, Xb, xh, xl);

        {
            GemmP p{};
            p.Ah[0] = xh; p.Al[0] = xl; p.Wh[0] = w1h + wf; p.Wl[0] = w1l + wf;
            p.bias[0] = b1 + l * FFNn; p.Ch[0] = hh; p.Cl[0] = hl;
            gemm2<<<dim3(8, 64, 1), 128, G2_SMEM>>>(p, FFNn, Dn, 2);
        }
        {
            GemmP p{};
            p.Ah[0] = hh; p.Al[0] = hl; p.Wh[0] = w2h + wf; p.Wl[0] = w2l + wf;
            p.bias[0] = b2 + l * Dn; p.C[0] = Yb;
            gemm2<<<dim3(2, 64, 1), 128, G2_SMEM>>>(p, Dn, FFNn, 0);
        }

        ln2_scatter_kernel<<<ROWS, 256>>>(Xb, Yb, g2 + l * Dn, be2 + l * Dn,
                                          out, il, fnum);
    }
}

// round 7
// speedup vs baseline: 2.5441x; 1.0021x over previous
#include <cuda_runtime.h>
#include <cuda_bf16.h>
#include <cstdint>

// ---------------------------------------------------------------------------
// Focus-DETR encoder — round 7: LN fused into GEMM epilogues, single wprep.
// ---------------------------------------------------------------------------

#define L_LAYERS 6
#define Bn 4
#define NN 23890
#define Kn 1024
#define Dn 256
#define Hn 8
#define HDn 32
#define FFNn 1024
#define NCLSn 15

#define ROWS (Bn * Kn)          // 4096
#define RD   (ROWS * Dn)        // 1048576 elements

// ---------------- scratch carving ----------------
constexpr size_t SZ_F  = (size_t)RD * 4;
constexpr size_t SZ_B  = (size_t)RD * 2;
constexpr size_t SZ_H  = (size_t)ROWS * FFNn * 2;
constexpr size_t SZ_WD = (size_t)L_LAYERS * Dn * Dn * 2;
constexpr size_t SZ_W1 = (size_t)L_LAYERS * Dn * FFNn * 2;

constexpr size_t OF_TGT = 0;
constexpr size_t OF_XB  = OF_TGT + SZ_F;
constexpr size_t OF_QKH = OF_XB  + SZ_F;
constexpr size_t OF_QKL = OF_QKH + SZ_B;
constexpr size_t OF_TGH = OF_QKL + SZ_B;
constexpr size_t OF_TGL = OF_TGH + SZ_B;
constexpr size_t OF_QH  = OF_TGL + SZ_B;
constexpr size_t OF_QL  = OF_QH  + SZ_B;
constexpr size_t OF_KH  = OF_QL  + SZ_B;
constexpr size_t OF_KL  = OF_KH  + SZ_B;
constexpr size_t OF_VH  = OF_KL  + SZ_B;
constexpr size_t OF_VL  = OF_VH  + SZ_B;
constexpr size_t OF_ATH = OF_VL  + SZ_B;
constexpr size_t OF_ATL = OF_ATH + SZ_B;
constexpr size_t OF_XH  = OF_ATL + SZ_B;
constexpr size_t OF_XL  = OF_XH  + SZ_B;
constexpr size_t OF_HH  = OF_XL  + SZ_B;
constexpr size_t OF_HL  = OF_HH  + SZ_H;
constexpr size_t OF_WQH = OF_HL  + SZ_H;
constexpr size_t OF_WQL = OF_WQH + SZ_WD;
constexpr size_t OF_WKH = OF_WQL + SZ_WD;
constexpr size_t OF_WKL = OF_WKH + SZ_WD;
constexpr size_t OF_WVH = OF_WKL + SZ_WD;
constexpr size_t OF_WVL = OF_WVH + SZ_WD;
constexpr size_t OF_WOH = OF_WVL + SZ_WD;
constexpr size_t OF_WOL = OF_WOH + SZ_WD;
constexpr size_t OF_W1H = OF_WOL + SZ_WD;
constexpr size_t OF_W1L = OF_W1H + SZ_W1;
constexpr size_t OF_W2H = OF_W1L + SZ_W1;
constexpr size_t OF_W2L = OF_W2H + SZ_W1;
constexpr size_t G_TOTAL = OF_W2L + SZ_W1;

__device__ __align__(1024) unsigned char g_mem[G_TOTAL];

// ============================ PTX helpers ==================================

__device__ __forceinline__ uint32_t smem_u32(const void* p) {
    uint32_t a;
    asm("{ .reg .u64 t; cvta.to.shared.u64 t, %1; cvt.u32.u64 %0, t; }"
        : "=r"(a) : "l"(p));
    return a;
}

#define CP16(sa, ga)                                                            \
    asm volatile("cp.async.ca.shared.global [%0], [%1], 16;"                    \
                 :: "r"(sa), "l"(__cvta_generic_to_global(ga)))
#define CP_COMMIT() asm volatile("cp.async.commit_group;" ::: "memory")
#define CP_WAIT0()  asm volatile("cp.async.wait_group 0;" ::: "memory")
#define CP_WAIT1()  asm volatile("cp.async.wait_group 1;" ::: "memory")

#define LDSM4(r, addr)                                                          \
    asm volatile("ldmatrix.sync.aligned.m8n8.x4.shared.b16 {%0,%1,%2,%3}, [%4];"\
        : "=r"((r)[0]), "=r"((r)[1]), "=r"((r)[2]), "=r"((r)[3]) : "r"(addr))

#define MMA_BF16(d, a, b0, b1)                                                  \
    asm volatile("mma.sync.aligned.m16n8k16.row.col.f32.bf16.bf16.f32 "         \
        "{%0,%1,%2,%3}, {%4,%5,%6,%7}, {%8,%9}, {%0,%1,%2,%3};"                 \
        : "+f"((d)[0]), "+f"((d)[1]), "+f"((d)[2]), "+f"((d)[3])                \
        : "r"((a)[0]), "r"((a)[1]), "r"((a)[2]), "r"((a)[3]), "r"(b0), "r"(b1))

__device__ __forceinline__ void split_bf16(float v, __nv_bfloat16& h, __nv_bfloat16& l) {
    h = __float2bfloat16(v);
    l = __float2bfloat16(v - __bfloat162float(h));
}

__device__ __forceinline__ uint32_t bf2_u32(__nv_bfloat16 a, __nv_bfloat16 b) {
    union { __nv_bfloat162 v; uint32_t u; } cvt;
    cvt.v = __halves2bfloat162(a, b);
    return cvt.u;
}

__device__ __forceinline__ void split2_pack(float v0, float v1,
                                            uint32_t& hi, uint32_t& lo) {
    __nv_bfloat16 h0, l0, h1, l1;
    split_bf16(v0, h0, l0);
    split_bf16(v1, h1, l1);
    hi = bf2_u32(h0, h1);
    lo = bf2_u32(l0, l1);
}

__device__ __forceinline__ float ex2(float x) {
    float r;
    asm("ex2.approx.ftz.f32 %0, %1;" : "=f"(r) : "f"(x));
    return r;
}

// ================== weight prep: all weights, one launch ===================
struct WprepP {
    const float* src[6];
    __nv_bfloat16 *dh[6], *dl[6];
};

__global__ __launch_bounds__(256) void wprep_all(WprepP p)
{
    __shared__ float tile[32][33];
    int bid = blockIdx.x;
    int g, layer, kt, nt, Kd, N;
    if (bid < 1536) {
        g = bid / 384; int r = bid % 384;
        layer = r >> 6; int t = r & 63;
        kt = t >> 3; nt = t & 7; Kd = 256; N = 256;
    } else if (bid < 3072) {
        g = 4; int r = bid - 1536;
        layer = r >> 8; int t = r & 255;
        kt = t >> 5; nt = t & 31; Kd = 256; N = 1024;
    } else {
        g = 5; int r = bid - 3072;
        layer = r >> 8; int t = r & 255;
        kt = t >> 3; nt = t & 7; Kd = 1024; N = 256;
    }
    const int k0 = kt << 5, n0 = nt << 5;
    const int tx = threadIdx.x & 31, ty = threadIdx.x >> 5;

    const float* Wp = p.src[g] + (size_t)layer * Kd * N;
#pragma unroll
    for (int r = ty; r < 32; r += 8)
        tile[r][tx] = Wp[(size_t)(k0 + r) * N + n0 + tx];
    __syncthreads();

    __nv_bfloat16* Hp = p.dh[g] + ((size_t)layer * N + n0) * Kd + k0;
    __nv_bfloat16* Lp = p.dl[g] + ((size_t)layer * N + n0) * Kd + k0;
#pragma unroll
    for (int r = ty; r < 32; r += 8) {
        float v = tile[tx][r];
        __nv_bfloat16 h, lo; split_bf16(v, h, lo);
        Hp[(size_t)r * Kd + tx] = h;
        Lp[(size_t)r * Kd + tx] = lo;
    }
}

// ============================ bf16x3 GEMM ==================================
// modes: 2 relu + bf16 hi/lo out (FFN1); 3 attention QKV layout
struct GemmP {
    const __nv_bfloat16 *Ah[3], *Al[3], *Wh[3], *Wl[3];
    const float* bias[3];
    float* C[3];
    __nv_bfloat16 *Ch[3], *Cl[3];
};

#define G2_AH 0
#define G2_AL 5120
#define G2_BH 10240
#define G2_BL 20480
#define G2_BUF 30720
#define G2_SMEM (2 * G2_BUF)

__global__ __launch_bounds__(128) void gemm2(GemmP p, int Ncols, int Kd, int mode)
{
    extern __shared__ __align__(16) char smem[];
    const uint32_t sb = smem_u32(smem);

    const int z    = blockIdx.z;
    const __nv_bfloat16* Ah = p.Ah[z];
    const __nv_bfloat16* Al = p.Al[z];
    const __nv_bfloat16* Wh = p.Wh[z];
    const __nv_bfloat16* Wl = p.Wl[z];

    const int tid  = threadIdx.x;
    const int lane = tid & 31;
    const int wn   = tid >> 5;
    const int bm   = blockIdx.y << 6;
    const int bn   = blockIdx.x << 7;

    float acc[4][4][4];
#pragma unroll
    for (int i = 0; i < 4; i++)
#pragma unroll
        for (int j = 0; j < 4; j++)
#pragma unroll
            for (int q = 0; q < 4; q++) acc[i][j][q] = 0.0f;

    const int a_r = lane & 15;
    const int a_c = (lane >> 4) << 3;
    const int b_r = wn * 32 + (lane & 7) + ((lane >> 4) << 3);
    const int b_c = ((lane >> 3) & 1) << 3;

    const int nc = Kd >> 5;

    auto issue = [&](int c, int buf) {
        const uint32_t sa = sb + buf * G2_BUF;
        const size_t kb = (size_t)(c << 5) * 2;
#pragma unroll
        for (int i = 0; i < 2; i++) {
            int s = tid + (i << 7);
            int row = s >> 2, seg = s & 3;
            size_t go = ((size_t)(bm + row) * Kd) * 2 + kb + seg * 16;
            uint32_t so = sa + row * 80 + seg * 16;
            CP16(so + G2_AH, (const char*)Ah + go);
            CP16(so + G2_AL, (const char*)Al + go);
        }
#pragma unroll
        for (int i = 0; i < 4; i++) {
            int s = tid + (i << 7);
            int row = s >> 2, seg = s & 3;
            size_t go = ((size_t)(bn + row) * Kd) * 2 + kb + seg * 16;
            uint32_t so = sa + row * 80 + seg * 16;
            CP16(so + G2_BH, (const char*)Wh + go);
            CP16(so + G2_BL, (const char*)Wl + go);
        }
        CP_COMMIT();
    };

    issue(0, 0);

    for (int c = 0; c < nc; c++) {
        const int buf = c & 1;
        if (c + 1 < nc) { issue(c + 1, buf ^ 1); CP_WAIT1(); }
        else           { CP_WAIT0(); }
        __syncthreads();

        const uint32_t sa = sb + buf * G2_BUF;
#pragma unroll
        for (int ks = 0; ks < 2; ks++) {
            uint32_t ah[4][4], al[4][4];
#pragma unroll
            for (int mb = 0; mb < 4; mb++) {
                uint32_t ao = sa + (uint32_t)(a_r + mb * 16) * 80 + (ks * 16 + a_c) * 2;
                LDSM4(ah[mb], ao + G2_AH);
                LDSM4(al[mb], ao + G2_AL);
            }
            uint32_t bh[2][4], bl[2][4];
#pragma unroll
            for (int np = 0; np < 2; np++) {
                uint32_t bo = sa + (uint32_t)(b_r + np * 16) * 80 + (ks * 16 + b_c) * 2;
                LDSM4(bh[np], bo + G2_BH);
                LDSM4(bl[np], bo + G2_BL);
            }
#pragma unroll
            for (int mb = 0; mb < 4; mb++)
#pragma unroll
                for (int nb = 0; nb < 4; nb++) {
                    const int np = nb >> 1, sl = (nb & 1) << 1;
                    MMA_BF16(acc[mb][nb], ah[mb], bh[np][sl], bh[np][sl + 1]);
                    MMA_BF16(acc[mb][nb], al[mb], bh[np][sl], bh[np][sl + 1]);
                    MMA_BF16(acc[mb][nb], ah[mb], bl[np][sl], bl[np][sl + 1]);
                }
        }
        __syncthreads();
    }

    const float* bias = p.bias[z];
    const int r0 = bm + (lane >> 2);
    const int c0 = bn + wn * 32 + ((lane & 3) << 1);

    if (mode == 2) {
        __nv_bfloat16* Ch = p.Ch[z];
        __nv_bfloat16* Cl = p.Cl[z];
#pragma unroll
        for (int mb = 0; mb < 4; mb++)
#pragma unroll
            for (int nb = 0; nb < 4; nb++) {
                int rr = r0 + mb * 16, cc = c0 + nb * 8;
                float bb0 = bias[cc], bb1 = bias[cc + 1];
#pragma unroll
                for (int hrow = 0; hrow < 2; hrow++) {
                    int r = rr + hrow * 8;
                    float v0 = fmaxf(acc[mb][nb][2 * hrow]     + bb0, 0.0f);
                    float v1 = fmaxf(acc[mb][nb][2 * hrow + 1] + bb1, 0.0f);
                    uint32_t hw, lw;
                    split2_pack(v0, v1, hw, lw);
                    *(uint32_t*)(Ch + (size_t)r * Ncols + cc) = hw;
                    *(uint32_t*)(Cl + (size_t)r * Ncols + cc) = lw;
                }
            }
    } else {    // mode 3: attention QKV layout
        __nv_bfloat16* Ch = p.Ch[z];
        __nv_bfloat16* Cl = p.Cl[z];
#pragma unroll
        for (int mb = 0; mb < 4; mb++)
#pragma unroll
            for (int nb = 0; nb < 4; nb++) {
                int rr = r0 + mb * 16, cc = c0 + nb * 8;
                float bb0 = bias[cc], bb1 = bias[cc + 1];
                int bh = ((rr >> 10) << 3) + (cc >> 5);
                int d  = cc & 31;
#pragma unroll
                for (int hrow = 0; hrow < 2; hrow++) {
                    int r = rr + hrow * 8;
                    int q = r & 1023;
                    float v0 = acc[mb][nb][2 * hrow]     + bb0;
                    float v1 = acc[mb][nb][2 * hrow + 1] + bb1;
                    __nv_bfloat16 h0, l0, h1, l1;
                    split_bf16(v0, h0, l0);
                    split_bf16(v1, h1, l1);
                    if (z < 2) {
                        size_t a = ((size_t)bh * 1024 + q) * 32 + d;
                        *(uint32_t*)(Ch + a) = bf2_u32(h0, h1);
                        *(uint32_t*)(Cl + a) = bf2_u32(l0, l1);
                    } else {
                        size_t a = ((size_t)bh * 32 + d) * 1024 + q;
                        Ch[a] = h0; Ch[a + 1024] = h1;
                        Cl[a] = l0; Cl[a + 1024] = l1;
                    }
                }
            }
    }
}

// ================= GEMM + LayerNorm fused (O-proj / FFN2) ==================
// C[row][0..255] = A @ W^T + bias;  v = res + C;  y = LN(v)
// Tile 32 rows x 256 cols, 256 threads (8 warps, warp w owns cols [32w,32w+32)).
// mode 1: y -> Xout fp32 + Xh/Xl bf16 split   (post O-proj, res = tgt)
// mode 2: y -> ragged scatter into out        (post FFN2,  res = Xb)
#define GL_AH 0
#define GL_AL 2560
#define GL_BH 5120
#define GL_BL 25600
#define GL_BUF 46080
#define GL_RED   92160          // 32 rows x 8 warps x float2
#define GL_BIAS  94208
#define GL_GAM   95232
#define GL_BET   96256
#define GL_SMEM  97280

__global__ __launch_bounds__(256) void gemm_ln(
    const __nv_bfloat16* __restrict__ Ah, const __nv_bfloat16* __restrict__ Al,
    const __nv_bfloat16* __restrict__ Wh, const __nv_bfloat16* __restrict__ Wl,
    const float* __restrict__ bias, const float* __restrict__ gam,
    const float* __restrict__ bet, const float* __restrict__ res,
    float* __restrict__ Xout, __nv_bfloat16* __restrict__ Xh,
    __nv_bfloat16* __restrict__ Xl,
    float* __restrict__ out, const int* __restrict__ il,
    const int* __restrict__ fnum,
    int Kd, int mode)
{
    extern __shared__ __align__(16) char smem[];
    const uint32_t sb = smem_u32(smem);

    const int tid  = threadIdx.x;
    const int lane = tid & 31;
    const int w    = tid >> 5;
    const int bm   = blockIdx.y << 5;

    // stage LN params
    ((float*)(smem + GL_BIAS))[tid] = bias[tid];
    ((float*)(smem + GL_GAM))[tid]  = gam[tid];
    ((float*)(smem + GL_BET))[tid]  = bet[tid];

    float acc[2][4][4];
#pragma unroll
    for (int i = 0; i < 2; i++)
#pragma unroll
        for (int j = 0; j < 4; j++)
#pragma unroll
            for (int q = 0; q < 4; q++) acc[i][j][q] = 0.0f;

    const int a_r = lane & 15;
    const int a_c = (lane >> 4) << 3;
    const int b_rr = (lane & 7) + ((lane >> 4) << 3);
    const int b_cc = ((lane >> 3) & 1) << 3;

    const int nc = Kd >> 5;

    auto issue = [&](int c, int buf) {
        const uint32_t sa = sb + buf * GL_BUF;
        const size_t kb = (size_t)(c << 5) * 2;
        if (tid < 128) {                       // A: 32 rows x 4 segs
            int row = tid >> 2, seg = tid & 3;
            size_t go = ((size_t)(bm + row) * Kd) * 2 + kb + seg * 16;
            uint32_t so = sa + row * 80 + seg * 16;
            CP16(so + GL_AH, (const char*)Ah + go);
            CP16(so + GL_AL, (const char*)Al + go);
        }
#pragma unroll
        for (int i = 0; i < 4; i++) {          // B: 256 rows x 4 segs
            int s = tid + (i << 8);
            int row = s >> 2, seg = s & 3;
            size_t go = ((size_t)row * Kd) * 2 + kb + seg * 16;
            uint32_t so = sa + row * 80 + seg * 16;
            CP16(so + GL_BH, (const char*)Wh + go);
            CP16(so + GL_BL, (const char*)Wl + go);
        }
        CP_COMMIT();
    };

    issue(0, 0);

    for (int c = 0; c < nc; c++) {
        const int buf = c & 1;
        if (c + 1 < nc) { issue(c + 1, buf ^ 1); CP_WAIT1(); }
        else           { CP_WAIT0(); }
        __syncthreads();

        const uint32_t sa = sb + buf * GL_BUF;
#pragma unroll
        for (int ks = 0; ks < 2; ks++) {
            uint32_t ah[2][4], al[2][4];
#pragma unroll
            for (int mb = 0; mb < 2; mb++) {
                uint32_t ao = sa + (uint32_t)(mb * 16 + a_r) * 80 + (ks * 16 + a_c) * 2;
                LDSM4(ah[mb], ao + GL_AH);
                LDSM4(al[mb], ao + GL_AL);
            }
            uint32_t bh[2][4], bl[2][4];
#pragma unroll
            for (int np = 0; np < 2; np++) {
                uint32_t bo = sa + (uint32_t)(w * 32 + np * 16 + b_rr) * 80
                            + (ks * 16 + b_cc) * 2;
                LDSM4(bh[np], bo + GL_BH);
                LDSM4(bl[np], bo + GL_BL);
            }
#pragma unroll
            for (int mb = 0; mb < 2; mb++)
#pragma unroll
                for (int nb = 0; nb < 4; nb++) {
                    const int np = nb >> 1, sl = (nb & 1) << 1;
                    MMA_BF16(acc[mb][nb], ah[mb], bh[np][sl], bh[np][sl + 1]);
                    MMA_BF16(acc[mb][nb], al[mb], bh[np][sl], bh[np][sl + 1]);
                    MMA_BF16(acc[mb][nb], ah[mb], bl[np][sl], bl[np][sl + 1]);
                }
        }
        __syncthreads();
    }

    // ---- epilogue: v = res + C + bias; overwrite acc with v; reduce ----
    const float* bias_s = (const float*)(smem + GL_BIAS);
    float2* red = (float2*)(smem + GL_RED);

#pragma unroll
    for (int mb = 0; mb < 2; mb++) {
        float sA = 0.f, qA = 0.f, sB = 0.f, qB = 0.f;
#pragma unroll
        for (int nb = 0; nb < 4; nb++) {
            int cc = w * 32 + nb * 8 + ((lane & 3) << 1);
            int rA = bm + mb * 16 + (lane >> 2);
            int rB = rA + 8;
            float2 resA = *(const float2*)(res + (size_t)rA * Dn + cc);
            float2 resB = *(const float2*)(res + (size_t)rB * Dn + cc);
            float bb0 = bias_s[cc], bb1 = bias_s[cc + 1];
            float v;
            v = acc[mb][nb][0] + bb0 + resA.x; acc[mb][nb][0] = v; sA += v; qA += v * v;
            v = acc[mb][nb][1] + bb1 + resA.y; acc[mb][nb][1] = v; sA += v; qA += v * v;
            v = acc[mb][nb][2] + bb0 + resB.x; acc[mb][nb][2] = v; sB += v; qB += v * v;
            v = acc[mb][nb][3] + bb1 + resB.y; acc[mb][nb][3] = v; sB += v; qB += v * v;
        }
        sA += __shfl_xor_sync(0xffffffffu, sA, 1); qA += __shfl_xor_sync(0xffffffffu, qA, 1);
        sA += __shfl_xor_sync(0xffffffffu, sA, 2); qA += __shfl_xor_sync(0xffffffffu, qA, 2);
        sB += __shfl_xor_sync(0xffffffffu, sB, 1); qB += __shfl_xor_sync(0xffffffffu, qB, 1);
        sB += __shfl_xor_sync(0xffffffffu, sB, 2); qB += __shfl_xor_sync(0xffffffffu, qB, 2);
        if ((lane & 3) == 0) {
            int rlA = mb * 16 + (lane >> 2);
            red[rlA * 8 + w] = make_float2(sA, qA);
            red[(rlA + 8) * 8 + w] = make_float2(sB, qB);
        }
    }
    __syncthreads();

    const float* gam_s = (const float*)(smem + GL_GAM);
    const float* bet_s = (const float*)(smem + GL_BET);
    const int b = bm >> 10;
    int fn = 0;
    if (mode == 2) fn = fnum[b];

#pragma unroll
    for (int mb = 0; mb < 2; mb++) {
#pragma unroll
        for (int hrow = 0; hrow < 2; hrow++) {
            int rl = mb * 16 + hrow * 8 + (lane >> 2);
            int row = bm + rl;
            float su = 0.f, sq = 0.f;
#pragma unroll
            for (int w2 = 0; w2 < 8; w2++) {
                float2 r2 = red[rl * 8 + w2];
                su += r2.x; sq += r2.y;
            }
            float mu = su * (1.0f / Dn);
            float var = sq * (1.0f / Dn) - mu * mu;
            float rs = rsqrtf(var + 1e-5f);

            if (mode == 1) {
#pragma unroll
                for (int nb = 0; nb < 4; nb++) {
                    int cc = w * 32 + nb * 8 + ((lane & 3) << 1);
                    float y0 = (acc[mb][nb][2 * hrow]     - mu) * rs * gam_s[cc]     + bet_s[cc];
                    float y1 = (acc[mb][nb][2 * hrow + 1] - mu) * rs * gam_s[cc + 1] + bet_s[cc + 1];
                    size_t a = (size_t)row * Dn + cc;
                    *(float2*)(Xout + a) = make_float2(y0, y1);
                    uint32_t hw, lw;
                    split2_pack(y0, y1, hw, lw);
                    *(uint32_t*)(Xh + a) = hw;
                    *(uint32_t*)(Xl + a) = lw;
                }
            } else {
                int j = row & 1023;
                if (j < fn) {
                    int idx = il[row];
                    float* op = out + ((size_t)b * NN + idx) * Dn;
#pragma unroll
                    for (int nb = 0; nb < 4; nb++) {
                        int cc = w * 32 + nb * 8 + ((lane & 3) << 1);
                        float y0 = (acc[mb][nb][2 * hrow]     - mu) * rs * gam_s[cc]     + bet_s[cc];
                        float y1 = (acc[mb][nb][2 * hrow + 1] - mu) * rs * gam_s[cc + 1] + bet_s[cc + 1];
                        *(float2*)(op + cc) = make_float2(y0, y1);
                    }
                }
            }
        }
    }
}

// ====================== tensor-core flash attention ========================
#define AT_QH 0
#define AT_QL 10240
#define AT_K  20480             // + buf*10240 : Kh(5120) Kl(5120)
#define AT_V  40960             // + buf*9216  : Vh(4608) Vl(4608)
#define AT_SMEM 59392
#define BETA 0.2550165213f      // log2(e)/sqrt(32)

__global__ __launch_bounds__(128) void attn_tc(
    const __nv_bfloat16* __restrict__ Qh, const __nv_bfloat16* __restrict__ Ql,
    const __nv_bfloat16* __restrict__ Kh, const __nv_bfloat16* __restrict__ Kl,
    const __nv_bfloat16* __restrict__ Vh, const __nv_bfloat16* __restrict__ Vl,
    __nv_bfloat16* __restrict__ Oh, __nv_bfloat16* __restrict__ Ol)
{
    extern __shared__ __align__(16) char smem[];
    const uint32_t sb = smem_u32(smem);

    const int tid  = threadIdx.x;
    const int lane = tid & 31;
    const int warp = tid >> 5;
    const int bh   = blockIdx.x;
    const int q0   = blockIdx.y << 7;

    {
        const char* gqh = (const char*)(Qh + ((size_t)bh * 1024 + q0) * 32);
        const char* gql = (const char*)(Ql + ((size_t)bh * 1024 + q0) * 32);
#pragma unroll
        for (int i = 0; i < 4; i++) {
            int s = tid + (i << 7);
            int row = s >> 2, seg = s & 3;
            size_t go = (size_t)row * 64 + seg * 16;
            uint32_t so = (uint32_t)row * 80 + seg * 16;
            CP16(sb + AT_QH + so, gqh + go);
            CP16(sb + AT_QL + so, gql + go);
        }
    }

    auto issueKV = [&](int c, int buf) {
        const int kc = c << 6;
        const uint32_t sk = sb + AT_K + buf * 10240;
        const uint32_t sv = sb + AT_V + buf * 9216;
        const char* gkh = (const char*)(Kh + ((size_t)bh * 1024 + kc) * 32);
        const char* gkl = (const char*)(Kl + ((size_t)bh * 1024 + kc) * 32);
#pragma unroll
        for (int i = 0; i < 2; i++) {
            int s = tid + (i << 7);
            int row = s >> 2, seg = s & 3;
            size_t go = (size_t)row * 64 + seg * 16;
            uint32_t so = (uint32_t)row * 80 + seg * 16;
            CP16(sk + so, gkh + go);
            CP16(sk + 5120 + so, gkl + go);
        }
        const char* gvh = (const char*)(Vh + (size_t)bh * 32 * 1024 + kc);
        const char* gvl = (const char*)(Vl + (size_t)bh * 32 * 1024 + kc);
#pragma unroll
        for (int i = 0; i < 2; i++) {
            int s = tid + (i << 7);
            int d = s >> 3, seg = s & 7;
            size_t go = (size_t)d * 2048 + seg * 16;
            uint32_t so = (uint32_t)d * 144 + seg * 16;
            CP16(sv + so, gvh + go);
            CP16(sv + 4608 + so, gvl + go);
        }
        CP_COMMIT();
    };

    issueKV(0, 0);

    float o[2][4][4];
    float m[2][2], l[2][2];
#pragma unroll
    for (int a = 0; a < 2; a++)
#pragma unroll
        for (int b = 0; b < 4; b++)
#pragma unroll
            for (int q = 0; q < 4; q++) o[a][b][q] = 0.0f;
#pragma unroll
    for (int a = 0; a < 2; a++) { m[a][0] = m[a][1] = -1e30f; l[a][0] = l[a][1] = 0.0f; }

    uint32_t qfh[2][2][4], qfl[2][2][4];

    const int a_r = lane & 15;
    const int a_c = (lane >> 4) << 3;
    const int b_rr = (lane & 7) + ((lane >> 4) << 3);
    const int b_cc = ((lane >> 3) & 1) << 3;

    for (int c = 0; c < 16; c++) {
        const int buf = c & 1;
        if (c + 1 < 16) { issueKV(c + 1, buf ^ 1); CP_WAIT1(); }
        else            { CP_WAIT0(); }
        __syncthreads();

        if (c == 0) {
#pragma unroll
            for (int mb = 0; mb < 2; mb++)
#pragma unroll
                for (int kk = 0; kk < 2; kk++) {
                    uint32_t ao = (uint32_t)(warp * 32 + mb * 16 + a_r) * 80
                                + (kk * 16 + a_c) * 2;
                    LDSM4(qfh[mb][kk], sb + AT_QH + ao);
                    LDSM4(qfl[mb][kk], sb + AT_QL + ao);
                }
        }

        const uint32_t sk = sb + AT_K + buf * 10240;
        const uint32_t sv = sb + AT_V + buf * 9216;

        float s[2][8][4];
#pragma unroll
        for (int a = 0; a < 2; a++)
#pragma unroll
            for (int b = 0; b < 8; b++)
#pragma unroll
                for (int q = 0; q < 4; q++) s[a][b][q] = 0.0f;

#pragma unroll
        for (int g = 0; g < 4; g++) {
            uint32_t kfh[2][4], kfl[2][4];
#pragma unroll
            for (int kk = 0; kk < 2; kk++) {
                uint32_t bo = (uint32_t)(g * 16 + b_rr) * 80 + (kk * 16 + b_cc) * 2;
                LDSM4(kfh[kk], sk + bo);
                LDSM4(kfl[kk], sk + 5120 + bo);
            }
#pragma unroll
            for (int mb = 0; mb < 2; mb++)
#pragma unroll
                for (int nb = 0; nb < 2; nb++) {
                    const int nt = g * 2 + nb, sl = nb << 1;
#pragma unroll
                    for (int kk = 0; kk < 2; kk++) {
                        MMA_BF16(s[mb][nt], qfh[mb][kk], kfh[kk][sl], kfh[kk][sl + 1]);
                        MMA_BF16(s[mb][nt], qfl[mb][kk], kfh[kk][sl], kfh[kk][sl + 1]);
                        MMA_BF16(s[mb][nt], qfh[mb][kk], kfl[kk][sl], kfl[kk][sl + 1]);
                    }
                }
        }

        float alpha[2][2], mb_new[2][2];
#pragma unroll
        for (int mb = 0; mb < 2; mb++) {
#pragma unroll
            for (int h = 0; h < 2; h++) {
                float mx = -1e30f;
#pragma unroll
                for (int nt = 0; nt < 8; nt++) {
                    mx = fmaxf(mx, s[mb][nt][2 * h]);
                    mx = fmaxf(mx, s[mb][nt][2 * h + 1]);
                }
                mx = fmaxf(mx, __shfl_xor_sync(0xffffffffu, mx, 1));
                mx = fmaxf(mx, __shfl_xor_sync(0xffffffffu, mx, 2));
                float mn = fmaxf(m[mb][h], mx);
                alpha[mb][h] = ex2((m[mb][h] - mn) * BETA);
                mb_new[mb][h] = mn;
                m[mb][h] = mn;
            }
        }
#pragma unroll
        for (int mb = 0; mb < 2; mb++) {
            float nm0 = mb_new[mb][0] * BETA, nm1 = mb_new[mb][1] * BETA;
#pragma unroll
            for (int nt = 0; nt < 8; nt++) {
                s[mb][nt][0] = ex2(fmaf(s[mb][nt][0], BETA, -nm0));
                s[mb][nt][1] = ex2(fmaf(s[mb][nt][1], BETA, -nm0));
                s[mb][nt][2] = ex2(fmaf(s[mb][nt][2], BETA, -nm1));
                s[mb][nt][3] = ex2(fmaf(s[mb][nt][3], BETA, -nm1));
            }
        }
#pragma unroll
        for (int mb = 0; mb < 2; mb++) {
#pragma unroll
            for (int h = 0; h < 2; h++) {
                float su = 0.0f;
#pragma unroll
                for (int nt = 0; nt < 8; nt++)
                    su += s[mb][nt][2 * h] + s[mb][nt][2 * h + 1];
                su += __shfl_xor_sync(0xffffffffu, su, 1);
                su += __shfl_xor_sync(0xffffffffu, su, 2);
                l[mb][h] = l[mb][h] * alpha[mb][h] + su;
            }
#pragma unroll
            for (int nb = 0; nb < 4; nb++) {
                o[mb][nb][0] *= alpha[mb][0];
                o[mb][nb][1] *= alpha[mb][0];
                o[mb][nb][2] *= alpha[mb][1];
                o[mb][nb][3] *= alpha[mb][1];
            }
        }

#pragma unroll
        for (int kt = 0; kt < 4; kt++) {
            uint32_t vfh[2][4], vfl[2][4];
#pragma unroll
            for (int g = 0; g < 2; g++) {
                uint32_t bo = (uint32_t)(g * 16 + b_rr) * 144 + (kt * 16 + b_cc) * 2;
                LDSM4(vfh[g], sv + bo);
                LDSM4(vfl[g], sv + 4608 + bo);
            }
#pragma unroll
            for (int mb = 0; mb < 2; mb++) {
                const int t0 = kt * 2, t1 = kt * 2 + 1;
                uint32_t ph[4], pl[4];
                split2_pack(s[mb][t0][0], s[mb][t0][1], ph[0], pl[0]);
                split2_pack(s[mb][t0][2], s[mb][t0][3], ph[1], pl[1]);
                split2_pack(s[mb][t1][0], s[mb][t1][1], ph[2], pl[2]);
                split2_pack(s[mb][t1][2], s[mb][t1][3], ph[3], pl[3]);
#pragma unroll
                for (int nb = 0; nb < 4; nb++) {
                    const int g = nb >> 1, sl = (nb & 1) << 1;
                    MMA_BF16(o[mb][nb], ph, vfh[g][sl], vfh[g][sl + 1]);
                    MMA_BF16(o[mb][nb], pl, vfh[g][sl], vfh[g][sl + 1]);
                    MMA_BF16(o[mb][nb], ph, vfl[g][sl], vfl[g][sl + 1]);
                }
            }
        }
        __syncthreads();
    }

    const int b  = bh >> 3;
    const int hh = bh & 7;
#pragma unroll
    for (int mb = 0; mb < 2; mb++) {
        float i0 = 1.0f / l[mb][0], i1 = 1.0f / l[mb][1];
#pragma unroll
        for (int h = 0; h < 2; h++) {
            int row = b * 1024 + q0 + warp * 32 + mb * 16 + h * 8 + (lane >> 2);
            float inv = h ? i1 : i0;
#pragma unroll
            for (int nb = 0; nb < 4; nb++) {
                int d = nb * 8 + ((lane & 3) << 1);
                float v0 = o[mb][nb][2 * h]     * inv;
                float v1 = o[mb][nb][2 * h + 1] * inv;
                uint32_t hw, lw;
                split2_pack(v0, v1, hw, lw);
                size_t a = (size_t)row * Dn + hh * 32 + d;
                *(uint32_t*)(Oh + a) = hw;
                *(uint32_t*)(Ol + a) = lw;
            }
        }
    }
}

// ---------------------------------------------------------------------------
// Gather + MCSP
// ---------------------------------------------------------------------------
__global__ __launch_bounds__(256) void gather_cls_kernel(
    const float* __restrict__ out, const float* __restrict__ qpos,
    const float* __restrict__ fgs, const int* __restrict__ il,
    const float* __restrict__ Wcls, const float* __restrict__ bcls,
    float* __restrict__ tgt,
    __nv_bfloat16* __restrict__ tgh, __nv_bfloat16* __restrict__ tgl,
    __nv_bfloat16* __restrict__ qkh, __nv_bfloat16* __restrict__ qkl)
{
    __shared__ float qs[Dn];
    __shared__ float sc[16];

    int row = blockIdx.x;
    int b   = row >> 10;
    int t   = threadIdx.x;
    int lane = t & 31, w = t >> 5;
    int idx = il[row];
    size_t src = ((size_t)b * NN + idx) * Dn + t;
    float qv = out[src];
    qs[t] = qv;
    __syncthreads();

#pragma unroll
    for (int ci = 0; ci < 2; ci++) {
        int c = w + ci * 8;
        if (c < NCLSn) {
            float sum = 0.0f;
#pragma unroll
            for (int j = 0; j < 8; j++) {
                int e = lane + (j << 5);
                sum += qs[e] * Wcls[e * NCLSn + c];
            }
#pragma unroll
            for (int o = 16; o; o >>= 1) sum += __shfl_down_sync(0xffffffffu, sum, o);
            if (lane == 0) sc[c] = sum + bcls[c];
        }
    }
    __syncthreads();

    float mx = sc[0];
#pragma unroll
    for (int c = 1; c < NCLSn; c++) mx = fmaxf(mx, sc[c]);
    float mc = (1.0f / (1.0f + __expf(-mx))) * fgs[(size_t)b * NN + idx];

    float tv = tgt[(size_t)row * Dn + t] = qv * mc;
    float qk = tv + qpos[src];
    size_t i = (size_t)row * Dn + t;
    __nv_bfloat16 h, lo;
    split_bf16(tv, h, lo); tgh[i] = h; tgl[i] = lo;
    split_bf16(qk, h, lo); qkh[i] = h; qkl[i] = lo;
}

// ---------------------------------------------------------------------------
// Host-side orchestration
// ---------------------------------------------------------------------------
extern "C" void kernel_launch(void* const* d_in, const int* in_sizes, int n_in,
                              void* d_out, int out_size)
{
    int qp_idx = (in_sizes[1] == 8) ? 4 : 1;

    const float* query = (const float*)d_in[0];
    const float* qpos  = (const float*)d_in[qp_idx];
    const float* fgs   = (const float*)d_in[6];
    const int*   fnum  = (const int*)d_in[7];
    const int*   inds  = (const int*)d_in[8];
    const float* Wq = (const float*)d_in[9],  *bq = (const float*)d_in[10];
    const float* Wk = (const float*)d_in[11], *bk = (const float*)d_in[12];
    const float* Wv = (const float*)d_in[13], *bv = (const float*)d_in[14];
    const float* Wo = (const float*)d_in[15], *bo = (const float*)d_in[16];
    const float* g1 = (const float*)d_in[17], *be1 = (const float*)d_in[18];
    const float* W1 = (const float*)d_in[19], *b1 = (const float*)d_in[20];
    const float* W2 = (const float*)d_in[21], *b2 = (const float*)d_in[22];
    const float* g2 = (const float*)d_in[23], *be2 = (const float*)d_in[24];
    const float* Wcls = (const float*)d_in[25], *bcls = (const float*)d_in[26];

    float* out = (float*)d_out;

    unsigned char* base = nullptr;
    cudaGetSymbolAddress((void**)&base, g_mem);
#define FP(off)  ((float*)(base + (off)))
#define BF(off)  ((__nv_bfloat16*)(base + (off)))

    float *tgt = FP(OF_TGT), *Xb = FP(OF_XB);
    __nv_bfloat16 *qkh = BF(OF_QKH), *qkl = BF(OF_QKL);
    __nv_bfloat16 *tgh = BF(OF_TGH), *tgl = BF(OF_TGL);
    __nv_bfloat16 *qh  = BF(OF_QH),  *ql  = BF(OF_QL);
    __nv_bfloat16 *kh  = BF(OF_KH),  *kl  = BF(OF_KL);
    __nv_bfloat16 *vh  = BF(OF_VH),  *vl  = BF(OF_VL);
    __nv_bfloat16 *ath = BF(OF_ATH), *atl = BF(OF_ATL);
    __nv_bfloat16 *xh  = BF(OF_XH),  *xl  = BF(OF_XL);
    __nv_bfloat16 *hh  = BF(OF_HH),  *hl  = BF(OF_HL);
    __nv_bfloat16 *wqh = BF(OF_WQH), *wql = BF(OF_WQL);
    __nv_bfloat16 *wkh = BF(OF_WKH), *wkl = BF(OF_WKL);
    __nv_bfloat16 *wvh = BF(OF_WVH), *wvl = BF(OF_WVL);
    __nv_bfloat16 *woh = BF(OF_WOH), *wol = BF(OF_WOL);
    __nv_bfloat16 *w1h = BF(OF_W1H), *w1l = BF(OF_W1L);
    __nv_bfloat16 *w2h = BF(OF_W2H), *w2l = BF(OF_W2L);

    cudaFuncSetAttribute(gemm2, cudaFuncAttributeMaxDynamicSharedMemorySize, G2_SMEM);
    cudaFuncSetAttribute(gemm_ln, cudaFuncAttributeMaxDynamicSharedMemorySize, GL_SMEM);
    cudaFuncSetAttribute(attn_tc, cudaFuncAttributeMaxDynamicSharedMemorySize, AT_SMEM);

    // ---- single weight-prep launch ----
    {
        WprepP wp{};
        wp.src[0] = Wq; wp.dh[0] = wqh; wp.dl[0] = wql;
        wp.src[1] = Wk; wp.dh[1] = wkh; wp.dl[1] = wkl;
        wp.src[2] = Wv; wp.dh[2] = wvh; wp.dl[2] = wvl;
        wp.src[3] = Wo; wp.dh[3] = woh; wp.dl[3] = wol;
        wp.src[4] = W1; wp.dh[4] = w1h; wp.dl[4] = w1l;
        wp.src[5] = W2; wp.dh[5] = w2h; wp.dl[5] = w2l;
        wprep_all<<<4608, 256>>>(wp);
    }

    cudaMemcpyAsync(out, query, sizeof(float) * (size_t)Bn * NN * Dn,
                    cudaMemcpyDeviceToDevice);

    for (int l = 0; l < L_LAYERS; l++) {
        const int* il = inds + (size_t)l * ROWS;
        const size_t wd = (size_t)l * Dn * Dn;
        const size_t wf = (size_t)l * Dn * FFNn;

        gather_cls_kernel<<<ROWS, 256>>>(out, qpos, fgs, il, Wcls, bcls,
                                         tgt, tgh, tgl, qkh, qkl);

        {   // QKV batched -> head layouts
            GemmP p{};
            p.Ah[0] = qkh; p.Al[0] = qkl; p.Wh[0] = wqh + wd; p.Wl[0] = wql + wd;
            p.bias[0] = bq + l * Dn; p.Ch[0] = qh; p.Cl[0] = ql;
            p.Ah[1] = qkh; p.Al[1] = qkl; p.Wh[1] = wkh + wd; p.Wl[1] = wkl + wd;
            p.bias[1] = bk + l * Dn; p.Ch[1] = kh; p.Cl[1] = kl;
            p.Ah[2] = tgh; p.Al[2] = tgl; p.Wh[2] = wvh + wd; p.Wl[2] = wvl + wd;
            p.bias[2] = bv + l * Dn; p.Ch[2] = vh; p.Cl[2] = vl;
            gemm2<<<dim3(2, 64, 3), 128, G2_SMEM>>>(p, Dn, Dn, 3);
        }

        attn_tc<<<dim3(Bn * Hn, Kn / 128), 128, AT_SMEM>>>(qh, ql, kh, kl, vh, vl,
                                                           ath, atl);

        // O projection + LN1 fused (res = tgt) -> Xb, xh, xl
        gemm_ln<<<dim3(1, ROWS / 32), 256, GL_SMEM>>>(
            ath, atl, woh + wd, wol + wd,
            bo + l * Dn, g1 + l * Dn, be1 + l * Dn, tgt,
            Xb, xh, xl, nullptr, nullptr, nullptr, Dn, 1);

        {   // FFN1 (relu, bf16 split out)
            GemmP p{};
            p.Ah[0] = xh; p.Al[0] = xl; p.Wh[0] = w1h + wf; p.Wl[0] = w1l + wf;
            p.bias[0] = b1 + l * FFNn; p.Ch[0] = hh; p.Cl[0] = hl;
            gemm2<<<dim3(8, 64, 1), 128, G2_SMEM>>>(p, FFNn, Dn, 2);
        }

        // FFN2 + LN2 + ragged scatter fused (res = Xb) -> out
        gemm_ln<<<dim3(1, ROWS / 32), 256, GL_SMEM>>>(
            hh, hl, w2h + wf, w2l + wf,
            b2 + l * Dn, g2 + l * Dn, be2 + l * Dn, Xb,
            nullptr, nullptr, nullptr, out, il, fnum, FFNn, 2);
    }
}

// round 8
// speedup vs baseline: 2.5642x; 1.0079x over previous
#include <cuda_runtime.h>
#include <cuda_bf16.h>
#include <cstdint>

// ---------------------------------------------------------------------------
// Focus-DETR encoder — round 8: attn_tc widened to 8 warps (16 q-rows/warp),
// one-wave grid, 2 CTAs/SM. Everything else as round 7.
// ---------------------------------------------------------------------------

#define L_LAYERS 6
#define Bn 4
#define NN 23890
#define Kn 1024
#define Dn 256
#define Hn 8
#define HDn 32
#define FFNn 1024
#define NCLSn 15

#define ROWS (Bn * Kn)          // 4096
#define RD   (ROWS * Dn)        // 1048576 elements

// ---------------- scratch carving ----------------
constexpr size_t SZ_F  = (size_t)RD * 4;
constexpr size_t SZ_B  = (size_t)RD * 2;
constexpr size_t SZ_H  = (size_t)ROWS * FFNn * 2;
constexpr size_t SZ_WD = (size_t)L_LAYERS * Dn * Dn * 2;
constexpr size_t SZ_W1 = (size_t)L_LAYERS * Dn * FFNn * 2;

constexpr size_t OF_TGT = 0;
constexpr size_t OF_XB  = OF_TGT + SZ_F;
constexpr size_t OF_QKH = OF_XB  + SZ_F;
constexpr size_t OF_QKL = OF_QKH + SZ_B;
constexpr size_t OF_TGH = OF_QKL + SZ_B;
constexpr size_t OF_TGL = OF_TGH + SZ_B;
constexpr size_t OF_QH  = OF_TGL + SZ_B;
constexpr size_t OF_QL  = OF_QH  + SZ_B;
constexpr size_t OF_KH  = OF_QL  + SZ_B;
constexpr size_t OF_KL  = OF_KH  + SZ_B;
constexpr size_t OF_VH  = OF_KL  + SZ_B;
constexpr size_t OF_VL  = OF_VH  + SZ_B;
constexpr size_t OF_ATH = OF_VL  + SZ_B;
constexpr size_t OF_ATL = OF_ATH + SZ_B;
constexpr size_t OF_XH  = OF_ATL + SZ_B;
constexpr size_t OF_XL  = OF_XH  + SZ_B;
constexpr size_t OF_HH  = OF_XL  + SZ_B;
constexpr size_t OF_HL  = OF_HH  + SZ_H;
constexpr size_t OF_WQH = OF_HL  + SZ_H;
constexpr size_t OF_WQL = OF_WQH + SZ_WD;
constexpr size_t OF_WKH = OF_WQL + SZ_WD;
constexpr size_t OF_WKL = OF_WKH + SZ_WD;
constexpr size_t OF_WVH = OF_WKL + SZ_WD;
constexpr size_t OF_WVL = OF_WVH + SZ_WD;
constexpr size_t OF_WOH = OF_WVL + SZ_WD;
constexpr size_t OF_WOL = OF_WOH + SZ_WD;
constexpr size_t OF_W1H = OF_WOL + SZ_WD;
constexpr size_t OF_W1L = OF_W1H + SZ_W1;
constexpr size_t OF_W2H = OF_W1L + SZ_W1;
constexpr size_t OF_W2L = OF_W2H + SZ_W1;
constexpr size_t G_TOTAL = OF_W2L + SZ_W1;

__device__ __align__(1024) unsigned char g_mem[G_TOTAL];

// ============================ PTX helpers ==================================

__device__ __forceinline__ uint32_t smem_u32(const void* p) {
    uint32_t a;
    asm("{ .reg .u64 t; cvta.to.shared.u64 t, %1; cvt.u32.u64 %0, t; }"
        : "=r"(a) : "l"(p));
    return a;
}

#define CP16(sa, ga)                                                            \
    asm volatile("cp.async.ca.shared.global [%0], [%1], 16;"                    \
                 :: "r"(sa), "l"(__cvta_generic_to_global(ga)))
#define CP_COMMIT() asm volatile("cp.async.commit_group;" ::: "memory")
#define CP_WAIT0()  asm volatile("cp.async.wait_group 0;" ::: "memory")
#define CP_WAIT1()  asm volatile("cp.async.wait_group 1;" ::: "memory")

#define LDSM4(r, addr)                                                          \
    asm volatile("ldmatrix.sync.aligned.m8n8.x4.shared.b16 {%0,%1,%2,%3}, [%4];"\
        : "=r"((r)[0]), "=r"((r)[1]), "=r"((r)[2]), "=r"((r)[3]) : "r"(addr))

#define MMA_BF16(d, a, b0, b1)                                                  \
    asm volatile("mma.sync.aligned.m16n8k16.row.col.f32.bf16.bf16.f32 "         \
        "{%0,%1,%2,%3}, {%4,%5,%6,%7}, {%8,%9}, {%0,%1,%2,%3};"                 \
        : "+f"((d)[0]), "+f"((d)[1]), "+f"((d)[2]), "+f"((d)[3])                \
        : "r"((a)[0]), "r"((a)[1]), "r"((a)[2]), "r"((a)[3]), "r"(b0), "r"(b1))

__device__ __forceinline__ void split_bf16(float v, __nv_bfloat16& h, __nv_bfloat16& l) {
    h = __float2bfloat16(v);
    l = __float2bfloat16(v - __bfloat162float(h));
}

__device__ __forceinline__ uint32_t bf2_u32(__nv_bfloat16 a, __nv_bfloat16 b) {
    union { __nv_bfloat162 v; uint32_t u; } cvt;
    cvt.v = __halves2bfloat162(a, b);
    return cvt.u;
}

__device__ __forceinline__ void split2_pack(float v0, float v1,
                                            uint32_t& hi, uint32_t& lo) {
    __nv_bfloat16 h0, l0, h1, l1;
    split_bf16(v0, h0, l0);
    split_bf16(v1, h1, l1);
    hi = bf2_u32(h0, h1);
    lo = bf2_u32(l0, l1);
}

__device__ __forceinline__ float ex2(float x) {
    float r;
    asm("ex2.approx.ftz.f32 %0, %1;" : "=f"(r) : "f"(x));
    return r;
}

// ================== weight prep: all weights, one launch ===================
struct WprepP {
    const float* src[6];
    __nv_bfloat16 *dh[6], *dl[6];
};

__global__ __launch_bounds__(256) void wprep_all(WprepP p)
{
    __shared__ float tile[32][33];
    int bid = blockIdx.x;
    int g, layer, kt, nt, Kd, N;
    if (bid < 1536) {
        g = bid / 384; int r = bid % 384;
        layer = r >> 6; int t = r & 63;
        kt = t >> 3; nt = t & 7; Kd = 256; N = 256;
    } else if (bid < 3072) {
        g = 4; int r = bid - 1536;
        layer = r >> 8; int t = r & 255;
        kt = t >> 5; nt = t & 31; Kd = 256; N = 1024;
    } else {
        g = 5; int r = bid - 3072;
        layer = r >> 8; int t = r & 255;
        kt = t >> 3; nt = t & 7; Kd = 1024; N = 256;
    }
    const int k0 = kt << 5, n0 = nt << 5;
    const int tx = threadIdx.x & 31, ty = threadIdx.x >> 5;

    const float* Wp = p.src[g] + (size_t)layer * Kd * N;
#pragma unroll
    for (int r = ty; r < 32; r += 8)
        tile[r][tx] = Wp[(size_t)(k0 + r) * N + n0 + tx];
    __syncthreads();

    __nv_bfloat16* Hp = p.dh[g] + ((size_t)layer * N + n0) * Kd + k0;
    __nv_bfloat16* Lp = p.dl[g] + ((size_t)layer * N + n0) * Kd + k0;
#pragma unroll
    for (int r = ty; r < 32; r += 8) {
        float v = tile[tx][r];
        __nv_bfloat16 h, lo; split_bf16(v, h, lo);
        Hp[(size_t)r * Kd + tx] = h;
        Lp[(size_t)r * Kd + tx] = lo;
    }
}

// ============================ bf16x3 GEMM ==================================
struct GemmP {
    const __nv_bfloat16 *Ah[3], *Al[3], *Wh[3], *Wl[3];
    const float* bias[3];
    float* C[3];
    __nv_bfloat16 *Ch[3], *Cl[3];
};

#define G2_AH 0
#define G2_AL 5120
#define G2_BH 10240
#define G2_BL 20480
#define G2_BUF 30720
#define G2_SMEM (2 * G2_BUF)

__global__ __launch_bounds__(128) void gemm2(GemmP p, int Ncols, int Kd, int mode)
{
    extern __shared__ __align__(16) char smem[];
    const uint32_t sb = smem_u32(smem);

    const int z    = blockIdx.z;
    const __nv_bfloat16* Ah = p.Ah[z];
    const __nv_bfloat16* Al = p.Al[z];
    const __nv_bfloat16* Wh = p.Wh[z];
    const __nv_bfloat16* Wl = p.Wl[z];

    const int tid  = threadIdx.x;
    const int lane = tid & 31;
    const int wn   = tid >> 5;
    const int bm   = blockIdx.y << 6;
    const int bn   = blockIdx.x << 7;

    float acc[4][4][4];
#pragma unroll
    for (int i = 0; i < 4; i++)
#pragma unroll
        for (int j = 0; j < 4; j++)
#pragma unroll
            for (int q = 0; q < 4; q++) acc[i][j][q] = 0.0f;

    const int a_r = lane & 15;
    const int a_c = (lane >> 4) << 3;
    const int b_r = wn * 32 + (lane & 7) + ((lane >> 4) << 3);
    const int b_c = ((lane >> 3) & 1) << 3;

    const int nc = Kd >> 5;

    auto issue = [&](int c, int buf) {
        const uint32_t sa = sb + buf * G2_BUF;
        const size_t kb = (size_t)(c << 5) * 2;
#pragma unroll
        for (int i = 0; i < 2; i++) {
            int s = tid + (i << 7);
            int row = s >> 2, seg = s & 3;
            size_t go = ((size_t)(bm + row) * Kd) * 2 + kb + seg * 16;
            uint32_t so = sa + row * 80 + seg * 16;
            CP16(so + G2_AH, (const char*)Ah + go);
            CP16(so + G2_AL, (const char*)Al + go);
        }
#pragma unroll
        for (int i = 0; i < 4; i++) {
            int s = tid + (i << 7);
            int row = s >> 2, seg = s & 3;
            size_t go = ((size_t)(bn + row) * Kd) * 2 + kb + seg * 16;
            uint32_t so = sa + row * 80 + seg * 16;
            CP16(so + G2_BH, (const char*)Wh + go);
            CP16(so + G2_BL, (const char*)Wl + go);
        }
        CP_COMMIT();
    };

    issue(0, 0);

    for (int c = 0; c < nc; c++) {
        const int buf = c & 1;
        if (c + 1 < nc) { issue(c + 1, buf ^ 1); CP_WAIT1(); }
        else           { CP_WAIT0(); }
        __syncthreads();

        const uint32_t sa = sb + buf * G2_BUF;
#pragma unroll
        for (int ks = 0; ks < 2; ks++) {
            uint32_t ah[4][4], al[4][4];
#pragma unroll
            for (int mb = 0; mb < 4; mb++) {
                uint32_t ao = sa + (uint32_t)(a_r + mb * 16) * 80 + (ks * 16 + a_c) * 2;
                LDSM4(ah[mb], ao + G2_AH);
                LDSM4(al[mb], ao + G2_AL);
            }
            uint32_t bh[2][4], bl[2][4];
#pragma unroll
            for (int np = 0; np < 2; np++) {
                uint32_t bo = sa + (uint32_t)(b_r + np * 16) * 80 + (ks * 16 + b_c) * 2;
                LDSM4(bh[np], bo + G2_BH);
                LDSM4(bl[np], bo + G2_BL);
            }
#pragma unroll
            for (int mb = 0; mb < 4; mb++)
#pragma unroll
                for (int nb = 0; nb < 4; nb++) {
                    const int np = nb >> 1, sl = (nb & 1) << 1;
                    MMA_BF16(acc[mb][nb], ah[mb], bh[np][sl], bh[np][sl + 1]);
                    MMA_BF16(acc[mb][nb], al[mb], bh[np][sl], bh[np][sl + 1]);
                    MMA_BF16(acc[mb][nb], ah[mb], bl[np][sl], bl[np][sl + 1]);
                }
        }
        __syncthreads();
    }

    const float* bias = p.bias[z];
    const int r0 = bm + (lane >> 2);
    const int c0 = bn + wn * 32 + ((lane & 3) << 1);

    if (mode == 2) {
        __nv_bfloat16* Ch = p.Ch[z];
        __nv_bfloat16* Cl = p.Cl[z];
#pragma unroll
        for (int mb = 0; mb < 4; mb++)
#pragma unroll
            for (int nb = 0; nb < 4; nb++) {
                int rr = r0 + mb * 16, cc = c0 + nb * 8;
                float bb0 = bias[cc], bb1 = bias[cc + 1];
#pragma unroll
                for (int hrow = 0; hrow < 2; hrow++) {
                    int r = rr + hrow * 8;
                    float v0 = fmaxf(acc[mb][nb][2 * hrow]     + bb0, 0.0f);
                    float v1 = fmaxf(acc[mb][nb][2 * hrow + 1] + bb1, 0.0f);
                    uint32_t hw, lw;
                    split2_pack(v0, v1, hw, lw);
                    *(uint32_t*)(Ch + (size_t)r * Ncols + cc) = hw;
                    *(uint32_t*)(Cl + (size_t)r * Ncols + cc) = lw;
                }
            }
    } else {    // mode 3: attention QKV layout
        __nv_bfloat16* Ch = p.Ch[z];
        __nv_bfloat16* Cl = p.Cl[z];
#pragma unroll
        for (int mb = 0; mb < 4; mb++)
#pragma unroll
            for (int nb = 0; nb < 4; nb++) {
                int rr = r0 + mb * 16, cc = c0 + nb * 8;
                float bb0 = bias[cc], bb1 = bias[cc + 1];
                int bh = ((rr >> 10) << 3) + (cc >> 5);
                int d  = cc & 31;
#pragma unroll
                for (int hrow = 0; hrow < 2; hrow++) {
                    int r = rr + hrow * 8;
                    int q = r & 1023;
                    float v0 = acc[mb][nb][2 * hrow]     + bb0;
                    float v1 = acc[mb][nb][2 * hrow + 1] + bb1;
                    __nv_bfloat16 h0, l0, h1, l1;
                    split_bf16(v0, h0, l0);
                    split_bf16(v1, h1, l1);
                    if (z < 2) {
                        size_t a = ((size_t)bh * 1024 + q) * 32 + d;
                        *(uint32_t*)(Ch + a) = bf2_u32(h0, h1);
                        *(uint32_t*)(Cl + a) = bf2_u32(l0, l1);
                    } else {
                        size_t a = ((size_t)bh * 32 + d) * 1024 + q;
                        Ch[a] = h0; Ch[a + 1024] = h1;
                        Cl[a] = l0; Cl[a + 1024] = l1;
                    }
                }
            }
    }
}

// ================= GEMM + LayerNorm fused (O-proj / FFN2) ==================
#define GL_AH 0
#define GL_AL 2560
#define GL_BH 5120
#define GL_BL 25600
#define GL_BUF 46080
#define GL_RED   92160
#define GL_BIAS  94208
#define GL_GAM   95232
#define GL_BET   96256
#define GL_SMEM  97280

__global__ __launch_bounds__(256) void gemm_ln(
    const __nv_bfloat16* __restrict__ Ah, const __nv_bfloat16* __restrict__ Al,
    const __nv_bfloat16* __restrict__ Wh, const __nv_bfloat16* __restrict__ Wl,
    const float* __restrict__ bias, const float* __restrict__ gam,
    const float* __restrict__ bet, const float* __restrict__ res,
    float* __restrict__ Xout, __nv_bfloat16* __restrict__ Xh,
    __nv_bfloat16* __restrict__ Xl,
    float* __restrict__ out, const int* __restrict__ il,
    const int* __restrict__ fnum,
    int Kd, int mode)
{
    extern __shared__ __align__(16) char smem[];
    const uint32_t sb = smem_u32(smem);

    const int tid  = threadIdx.x;
    const int lane = tid & 31;
    const int w    = tid >> 5;
    const int bm   = blockIdx.y << 5;

    ((float*)(smem + GL_BIAS))[tid] = bias[tid];
    ((float*)(smem + GL_GAM))[tid]  = gam[tid];
    ((float*)(smem + GL_BET))[tid]  = bet[tid];

    float acc[2][4][4];
#pragma unroll
    for (int i = 0; i < 2; i++)
#pragma unroll
        for (int j = 0; j < 4; j++)
#pragma unroll
            for (int q = 0; q < 4; q++) acc[i][j][q] = 0.0f;

    const int a_r = lane & 15;
    const int a_c = (lane >> 4) << 3;
    const int b_rr = (lane & 7) + ((lane >> 4) << 3);
    const int b_cc = ((lane >> 3) & 1) << 3;

    const int nc = Kd >> 5;

    auto issue = [&](int c, int buf) {
        const uint32_t sa = sb + buf * GL_BUF;
        const size_t kb = (size_t)(c << 5) * 2;
        if (tid < 128) {
            int row = tid >> 2, seg = tid & 3;
            size_t go = ((size_t)(bm + row) * Kd) * 2 + kb + seg * 16;
            uint32_t so = sa + row * 80 + seg * 16;
            CP16(so + GL_AH, (const char*)Ah + go);
            CP16(so + GL_AL, (const char*)Al + go);
        }
#pragma unroll
        for (int i = 0; i < 4; i++) {
            int s = tid + (i << 8);
            int row = s >> 2, seg = s & 3;
            size_t go = ((size_t)row * Kd) * 2 + kb + seg * 16;
            uint32_t so = sa + row * 80 + seg * 16;
            CP16(so + GL_BH, (const char*)Wh + go);
            CP16(so + GL_BL, (const char*)Wl + go);
        }
        CP_COMMIT();
    };

    issue(0, 0);

    for (int c = 0; c < nc; c++) {
        const int buf = c & 1;
        if (c + 1 < nc) { issue(c + 1, buf ^ 1); CP_WAIT1(); }
        else           { CP_WAIT0(); }
        __syncthreads();

        const uint32_t sa = sb + buf * GL_BUF;
#pragma unroll
        for (int ks = 0; ks < 2; ks++) {
            uint32_t ah[2][4], al[2][4];
#pragma unroll
            for (int mb = 0; mb < 2; mb++) {
                uint32_t ao = sa + (uint32_t)(mb * 16 + a_r) * 80 + (ks * 16 + a_c) * 2;
                LDSM4(ah[mb], ao + GL_AH);
                LDSM4(al[mb], ao + GL_AL);
            }
            uint32_t bh[2][4], bl[2][4];
#pragma unroll
            for (int np = 0; np < 2; np++) {
                uint32_t bo = sa + (uint32_t)(w * 32 + np * 16 + b_rr) * 80
                            + (ks * 16 + b_cc) * 2;
                LDSM4(bh[np], bo + GL_BH);
                LDSM4(bl[np], bo + GL_BL);
            }
#pragma unroll
            for (int mb = 0; mb < 2; mb++)
#pragma unroll
                for (int nb = 0; nb < 4; nb++) {
                    const int np = nb >> 1, sl = (nb & 1) << 1;
                    MMA_BF16(acc[mb][nb], ah[mb], bh[np][sl], bh[np][sl + 1]);
                    MMA_BF16(acc[mb][nb], al[mb], bh[np][sl], bh[np][sl + 1]);
                    MMA_BF16(acc[mb][nb], ah[mb], bl[np][sl], bl[np][sl + 1]);
                }
        }
        __syncthreads();
    }

    const float* bias_s = (const float*)(smem + GL_BIAS);
    float2* red = (float2*)(smem + GL_RED);

#pragma unroll
    for (int mb = 0; mb < 2; mb++) {
        float sA = 0.f, qA = 0.f, sB = 0.f, qB = 0.f;
#pragma unroll
        for (int nb = 0; nb < 4; nb++) {
            int cc = w * 32 + nb * 8 + ((lane & 3) << 1);
            int rA = bm + mb * 16 + (lane >> 2);
            int rB = rA + 8;
            float2 resA = *(const float2*)(res + (size_t)rA * Dn + cc);
            float2 resB = *(const float2*)(res + (size_t)rB * Dn + cc);
            float bb0 = bias_s[cc], bb1 = bias_s[cc + 1];
            float v;
            v = acc[mb][nb][0] + bb0 + resA.x; acc[mb][nb][0] = v; sA += v; qA += v * v;
            v = acc[mb][nb][1] + bb1 + resA.y; acc[mb][nb][1] = v; sA += v; qA += v * v;
            v = acc[mb][nb][2] + bb0 + resB.x; acc[mb][nb][2] = v; sB += v; qB += v * v;
            v = acc[mb][nb][3] + bb1 + resB.y; acc[mb][nb][3] = v; sB += v; qB += v * v;
        }
        sA += __shfl_xor_sync(0xffffffffu, sA, 1); qA += __shfl_xor_sync(0xffffffffu, qA, 1);
        sA += __shfl_xor_sync(0xffffffffu, sA, 2); qA += __shfl_xor_sync(0xffffffffu, qA, 2);
        sB += __shfl_xor_sync(0xffffffffu, sB, 1); qB += __shfl_xor_sync(0xffffffffu, qB, 1);
        sB += __shfl_xor_sync(0xffffffffu, sB, 2); qB += __shfl_xor_sync(0xffffffffu, qB, 2);
        if ((lane & 3) == 0) {
            int rlA = mb * 16 + (lane >> 2);
            red[rlA * 8 + w] = make_float2(sA, qA);
            red[(rlA + 8) * 8 + w] = make_float2(sB, qB);
        }
    }
    __syncthreads();

    const float* gam_s = (const float*)(smem + GL_GAM);
    const float* bet_s = (const float*)(smem + GL_BET);
    const int b = bm >> 10;
    int fn = 0;
    if (mode == 2) fn = fnum[b];

#pragma unroll
    for (int mb = 0; mb < 2; mb++) {
#pragma unroll
        for (int hrow = 0; hrow < 2; hrow++) {
            int rl = mb * 16 + hrow * 8 + (lane >> 2);
            int row = bm + rl;
            float su = 0.f, sq = 0.f;
#pragma unroll
            for (int w2 = 0; w2 < 8; w2++) {
                float2 r2 = red[rl * 8 + w2];
                su += r2.x; sq += r2.y;
            }
            float mu = su * (1.0f / Dn);
            float var = sq * (1.0f / Dn) - mu * mu;
            float rs = rsqrtf(var + 1e-5f);

            if (mode == 1) {
#pragma unroll
                for (int nb = 0; nb < 4; nb++) {
                    int cc = w * 32 + nb * 8 + ((lane & 3) << 1);
                    float y0 = (acc[mb][nb][2 * hrow]     - mu) * rs * gam_s[cc]     + bet_s[cc];
                    float y1 = (acc[mb][nb][2 * hrow + 1] - mu) * rs * gam_s[cc + 1] + bet_s[cc + 1];
                    size_t a = (size_t)row * Dn + cc;
                    *(float2*)(Xout + a) = make_float2(y0, y1);
                    uint32_t hw, lw;
                    split2_pack(y0, y1, hw, lw);
                    *(uint32_t*)(Xh + a) = hw;
                    *(uint32_t*)(Xl + a) = lw;
                }
            } else {
                int j = row & 1023;
                if (j < fn) {
                    int idx = il[row];
                    float* op = out + ((size_t)b * NN + idx) * Dn;
#pragma unroll
                    for (int nb = 0; nb < 4; nb++) {
                        int cc = w * 32 + nb * 8 + ((lane & 3) << 1);
                        float y0 = (acc[mb][nb][2 * hrow]     - mu) * rs * gam_s[cc]     + bet_s[cc];
                        float y1 = (acc[mb][nb][2 * hrow + 1] - mu) * rs * gam_s[cc + 1] + bet_s[cc + 1];
                        *(float2*)(op + cc) = make_float2(y0, y1);
                    }
                }
            }
        }
    }
}

// ====================== tensor-core flash attention ========================
// 256 threads: 8 warps x 16 query rows. Grid (bh=32, qt=8): 128 queries/CTA.
// 2 CTAs/SM (forced by launch_bounds) -> one wave of 256 CTAs.
#define AT_QH 0
#define AT_QL 10240
#define AT_K  20480             // + buf*10240 : Kh(5120) Kl(5120)
#define AT_V  40960             // + buf*9216  : Vh(4608) Vl(4608)
#define AT_SMEM 59392
#define BETA 0.2550165213f      // log2(e)/sqrt(32)

__global__ __launch_bounds__(256, 2) void attn_tc(
    const __nv_bfloat16* __restrict__ Qh, const __nv_bfloat16* __restrict__ Ql,
    const __nv_bfloat16* __restrict__ Kh, const __nv_bfloat16* __restrict__ Kl,
    const __nv_bfloat16* __restrict__ Vh, const __nv_bfloat16* __restrict__ Vl,
    __nv_bfloat16* __restrict__ Oh, __nv_bfloat16* __restrict__ Ol)
{
    extern __shared__ __align__(16) char smem[];
    const uint32_t sb = smem_u32(smem);

    const int tid  = threadIdx.x;
    const int lane = tid & 31;
    const int warp = tid >> 5;           // 0..7, owns rows [16*warp, 16*warp+16)
    const int bh   = blockIdx.x;
    const int q0   = blockIdx.y << 7;

    // ---- Q stage (one-time): 128 rows x 64B, hi+lo ----
    {
        const char* gqh = (const char*)(Qh + ((size_t)bh * 1024 + q0) * 32);
        const char* gql = (const char*)(Ql + ((size_t)bh * 1024 + q0) * 32);
#pragma unroll
        for (int i = 0; i < 2; i++) {
            int s = tid + (i << 8);
            int row = s >> 2, seg = s & 3;
            size_t go = (size_t)row * 64 + seg * 16;
            uint32_t so = (uint32_t)row * 80 + seg * 16;
            CP16(sb + AT_QH + so, gqh + go);
            CP16(sb + AT_QL + so, gql + go);
        }
    }

    auto issueKV = [&](int c, int buf) {
        const int kc = c << 6;
        const uint32_t sk = sb + AT_K + buf * 10240;
        const uint32_t sv = sb + AT_V + buf * 9216;
        // K: 64 rows x 4 segs = 256 ops
        {
            const char* gkh = (const char*)(Kh + ((size_t)bh * 1024 + kc) * 32);
            const char* gkl = (const char*)(Kl + ((size_t)bh * 1024 + kc) * 32);
            int row = tid >> 2, seg = tid & 3;
            size_t go = (size_t)row * 64 + seg * 16;
            uint32_t so = (uint32_t)row * 80 + seg * 16;
            CP16(sk + so, gkh + go);
            CP16(sk + 5120 + so, gkl + go);
        }
        // V: 32 d-rows x 8 segs = 256 ops
        {
            const char* gvh = (const char*)(Vh + (size_t)bh * 32 * 1024 + kc);
            const char* gvl = (const char*)(Vl + (size_t)bh * 32 * 1024 + kc);
            int d = tid >> 3, seg = tid & 7;
            size_t go = (size_t)d * 2048 + seg * 16;
            uint32_t so = (uint32_t)d * 144 + seg * 16;
            CP16(sv + so, gvh + go);
            CP16(sv + 4608 + so, gvl + go);
        }
        CP_COMMIT();
    };

    issueKV(0, 0);

    float o[4][4];
    float m[2], l[2];
#pragma unroll
    for (int b = 0; b < 4; b++)
#pragma unroll
        for (int q = 0; q < 4; q++) o[b][q] = 0.0f;
    m[0] = m[1] = -1e30f; l[0] = l[1] = 0.0f;

    uint32_t qfh[2][4], qfl[2][4];       // [kk]

    const int a_r = lane & 15;
    const int a_c = (lane >> 4) << 3;
    const int b_rr = (lane & 7) + ((lane >> 4) << 3);
    const int b_cc = ((lane >> 3) & 1) << 3;

    for (int c = 0; c < 16; c++) {
        const int buf = c & 1;
        if (c + 1 < 16) { issueKV(c + 1, buf ^ 1); CP_WAIT1(); }
        else            { CP_WAIT0(); }
        __syncthreads();

        if (c == 0) {   // load Q frags once (16 rows per warp)
#pragma unroll
            for (int kk = 0; kk < 2; kk++) {
                uint32_t ao = (uint32_t)(warp * 16 + a_r) * 80 + (kk * 16 + a_c) * 2;
                LDSM4(qfh[kk], sb + AT_QH + ao);
                LDSM4(qfl[kk], sb + AT_QL + ao);
            }
        }

        const uint32_t sk = sb + AT_K + buf * 10240;
        const uint32_t sv = sb + AT_V + buf * 9216;

        // ---- S = Q K^T : 16 x 64 per warp ----
        float s[8][4];
#pragma unroll
        for (int b = 0; b < 8; b++)
#pragma unroll
            for (int q = 0; q < 4; q++) s[b][q] = 0.0f;

#pragma unroll
        for (int g = 0; g < 4; g++) {
            uint32_t kfh[2][4], kfl[2][4];
#pragma unroll
            for (int kk = 0; kk < 2; kk++) {
                uint32_t bo = (uint32_t)(g * 16 + b_rr) * 80 + (kk * 16 + b_cc) * 2;
                LDSM4(kfh[kk], sk + bo);
                LDSM4(kfl[kk], sk + 5120 + bo);
            }
#pragma unroll
            for (int nb = 0; nb < 2; nb++) {
                const int nt = g * 2 + nb, sl = nb << 1;
#pragma unroll
                for (int kk = 0; kk < 2; kk++) {
                    MMA_BF16(s[nt], qfh[kk], kfh[kk][sl], kfh[kk][sl + 1]);
                    MMA_BF16(s[nt], qfl[kk], kfh[kk][sl], kfh[kk][sl + 1]);
                    MMA_BF16(s[nt], qfh[kk], kfl[kk][sl], kfl[kk][sl + 1]);
                }
            }
        }

        // ---- online softmax ----
        float alpha[2], mn2[2];
#pragma unroll
        for (int h = 0; h < 2; h++) {
            float mx = -1e30f;
#pragma unroll
            for (int nt = 0; nt < 8; nt++) {
                mx = fmaxf(mx, s[nt][2 * h]);
                mx = fmaxf(mx, s[nt][2 * h + 1]);
            }
            mx = fmaxf(mx, __shfl_xor_sync(0xffffffffu, mx, 1));
            mx = fmaxf(mx, __shfl_xor_sync(0xffffffffu, mx, 2));
            float mn = fmaxf(m[h], mx);
            alpha[h] = ex2((m[h] - mn) * BETA);
            mn2[h] = mn;
            m[h] = mn;
        }
        {
            float nm0 = mn2[0] * BETA, nm1 = mn2[1] * BETA;
#pragma unroll
            for (int nt = 0; nt < 8; nt++) {
                s[nt][0] = ex2(fmaf(s[nt][0], BETA, -nm0));
                s[nt][1] = ex2(fmaf(s[nt][1], BETA, -nm0));
                s[nt][2] = ex2(fmaf(s[nt][2], BETA, -nm1));
                s[nt][3] = ex2(fmaf(s[nt][3], BETA, -nm1));
            }
        }
#pragma unroll
        for (int h = 0; h < 2; h++) {
            float su = 0.0f;
#pragma unroll
            for (int nt = 0; nt < 8; nt++)
                su += s[nt][2 * h] + s[nt][2 * h + 1];
            su += __shfl_xor_sync(0xffffffffu, su, 1);
            su += __shfl_xor_sync(0xffffffffu, su, 2);
            l[h] = l[h] * alpha[h] + su;
        }
#pragma unroll
        for (int nb = 0; nb < 4; nb++) {
            o[nb][0] *= alpha[0];
            o[nb][1] *= alpha[0];
            o[nb][2] *= alpha[1];
            o[nb][3] *= alpha[1];
        }

        // ---- O += P V ----
#pragma unroll
        for (int kt = 0; kt < 4; kt++) {
            uint32_t vfh[2][4], vfl[2][4];
#pragma unroll
            for (int g = 0; g < 2; g++) {
                uint32_t bo = (uint32_t)(g * 16 + b_rr) * 144 + (kt * 16 + b_cc) * 2;
                LDSM4(vfh[g], sv + bo);
                LDSM4(vfl[g], sv + 4608 + bo);
            }
            const int t0 = kt * 2, t1 = kt * 2 + 1;
            uint32_t ph[4], pl[4];
            split2_pack(s[t0][0], s[t0][1], ph[0], pl[0]);
            split2_pack(s[t0][2], s[t0][3], ph[1], pl[1]);
            split2_pack(s[t1][0], s[t1][1], ph[2], pl[2]);
            split2_pack(s[t1][2], s[t1][3], ph[3], pl[3]);
#pragma unroll
            for (int nb = 0; nb < 4; nb++) {
                const int g = nb >> 1, sl = (nb & 1) << 1;
                MMA_BF16(o[nb], ph, vfh[g][sl], vfh[g][sl + 1]);
                MMA_BF16(o[nb], pl, vfh[g][sl], vfh[g][sl + 1]);
                MMA_BF16(o[nb], ph, vfl[g][sl], vfl[g][sl + 1]);
            }
        }
        __syncthreads();
    }

    // ---- epilogue: normalize, split, store flat [row][256] ----
    const int b  = bh >> 3;
    const int hh = bh & 7;
    {
        float i0 = 1.0f / l[0], i1 = 1.0f / l[1];
#pragma unroll
        for (int h = 0; h < 2; h++) {
            int row = b * 1024 + q0 + warp * 16 + h * 8 + (lane >> 2);
            float inv = h ? i1 : i0;
#pragma unroll
            for (int nb = 0; nb < 4; nb++) {
                int d = nb * 8 + ((lane & 3) << 1);
                float v0 = o[nb][2 * h]     * inv;
                float v1 = o[nb][2 * h + 1] * inv;
                uint32_t hw, lw;
                split2_pack(v0, v1, hw, lw);
                size_t a = (size_t)row * Dn + hh * 32 + d;
                *(uint32_t*)(Oh + a) = hw;
                *(uint32_t*)(Ol + a) = lw;
            }
        }
    }
}

// ---------------------------------------------------------------------------
// Gather + MCSP
// ---------------------------------------------------------------------------
__global__ __launch_bounds__(256) void gather_cls_kernel(
    const float* __restrict__ out, const float* __restrict__ qpos,
    const float* __restrict__ fgs, const int* __restrict__ il,
    const float* __restrict__ Wcls, const float* __restrict__ bcls,
    float* __restrict__ tgt,
    __nv_bfloat16* __restrict__ tgh, __nv_bfloat16* __restrict__ tgl,
    __nv_bfloat16* __restrict__ qkh, __nv_bfloat16* __restrict__ qkl)
{
    __shared__ float qs[Dn];
    __shared__ float sc[16];

    int row = blockIdx.x;
    int b   = row >> 10;
    int t   = threadIdx.x;
    int lane = t & 31, w = t >> 5;
    int idx = il[row];
    size_t src = ((size_t)b * NN + idx) * Dn + t;
    float qv = out[src];
    qs[t] = qv;
    __syncthreads();

#pragma unroll
    for (int ci = 0; ci < 2; ci++) {
        int c = w + ci * 8;
        if (c < NCLSn) {
            float sum = 0.0f;
#pragma unroll
            for (int j = 0; j < 8; j++) {
                int e = lane + (j << 5);
                sum += qs[e] * Wcls[e * NCLSn + c];
            }
#pragma unroll
            for (int o = 16; o; o >>= 1) sum += __shfl_down_sync(0xffffffffu, sum, o);
            if (lane == 0) sc[c] = sum + bcls[c];
        }
    }
    __syncthreads();

    float mx = sc[0];
#pragma unroll
    for (int c = 1; c < NCLSn; c++) mx = fmaxf(mx, sc[c]);
    float mc = (1.0f / (1.0f + __expf(-mx))) * fgs[(size_t)b * NN + idx];

    float tv = tgt[(size_t)row * Dn + t] = qv * mc;
    float qk = tv + qpos[src];
    size_t i = (size_t)row * Dn + t;
    __nv_bfloat16 h, lo;
    split_bf16(tv, h, lo); tgh[i] = h; tgl[i] = lo;
    split_bf16(qk, h, lo); qkh[i] = h; qkl[i] = lo;
}

// ---------------------------------------------------------------------------
// Host-side orchestration
// ---------------------------------------------------------------------------
extern "C" void kernel_launch(void* const* d_in, const int* in_sizes, int n_in,
                              void* d_out, int out_size)
{
    int qp_idx = (in_sizes[1] == 8) ? 4 : 1;

    const float* query = (const float*)d_in[0];
    const float* qpos  = (const float*)d_in[qp_idx];
    const float* fgs   = (const float*)d_in[6];
    const int*   fnum  = (const int*)d_in[7];
    const int*   inds  = (const int*)d_in[8];
    const float* Wq = (const float*)d_in[9],  *bq = (const float*)d_in[10];
    const float* Wk = (const float*)d_in[11], *bk = (const float*)d_in[12];
    const float* Wv = (const float*)d_in[13], *bv = (const float*)d_in[14];
    const float* Wo = (const float*)d_in[15], *bo = (const float*)d_in[16];
    const float* g1 = (const float*)d_in[17], *be1 = (const float*)d_in[18];
    const float* W1 = (const float*)d_in[19], *b1 = (const float*)d_in[20];
    const float* W2 = (const float*)d_in[21], *b2 = (const float*)d_in[22];
    const float* g2 = (const float*)d_in[23], *be2 = (const float*)d_in[24];
    const float* Wcls = (const float*)d_in[25], *bcls = (const float*)d_in[26];

    float* out = (float*)d_out;

    unsigned char* base = nullptr;
    cudaGetSymbolAddress((void**)&base, g_mem);
#define FP(off)  ((float*)(base + (off)))
#define BF(off)  ((__nv_bfloat16*)(base + (off)))

    float *tgt = FP(OF_TGT), *Xb = FP(OF_XB);
    __nv_bfloat16 *qkh = BF(OF_QKH), *qkl = BF(OF_QKL);
    __nv_bfloat16 *tgh = BF(OF_TGH), *tgl = BF(OF_TGL);
    __nv_bfloat16 *qh  = BF(OF_QH),  *ql  = BF(OF_QL);
    __nv_bfloat16 *kh  = BF(OF_KH),  *kl  = BF(OF_KL);
    __nv_bfloat16 *vh  = BF(OF_VH),  *vl  = BF(OF_VL);
    __nv_bfloat16 *ath = BF(OF_ATH), *atl = BF(OF_ATL);
    __nv_bfloat16 *xh  = BF(OF_XH),  *xl  = BF(OF_XL);
    __nv_bfloat16 *hh  = BF(OF_HH),  *hl  = BF(OF_HL);
    __nv_bfloat16 *wqh = BF(OF_WQH), *wql = BF(OF_WQL);
    __nv_bfloat16 *wkh = BF(OF_WKH), *wkl = BF(OF_WKL);
    __nv_bfloat16 *wvh = BF(OF_WVH), *wvl = BF(OF_WVL);
    __nv_bfloat16 *woh = BF(OF_WOH), *wol = BF(OF_WOL);
    __nv_bfloat16 *w1h = BF(OF_W1H), *w1l = BF(OF_W1L);
    __nv_bfloat16 *w2h = BF(OF_W2H), *w2l = BF(OF_W2L);

    cudaFuncSetAttribute(gemm2, cudaFuncAttributeMaxDynamicSharedMemorySize, G2_SMEM);
    cudaFuncSetAttribute(gemm_ln, cudaFuncAttributeMaxDynamicSharedMemorySize, GL_SMEM);
    cudaFuncSetAttribute(attn_tc, cudaFuncAttributeMaxDynamicSharedMemorySize, AT_SMEM);

    {
        WprepP wp{};
        wp.src[0] = Wq; wp.dh[0] = wqh; wp.dl[0] = wql;
        wp.src[1] = Wk; wp.dh[1] = wkh; wp.dl[1] = wkl;
        wp.src[2] = Wv; wp.dh[2] = wvh; wp.dl[2] = wvl;
        wp.src[3] = Wo; wp.dh[3] = woh; wp.dl[3] = wol;
        wp.src[4] = W1; wp.dh[4] = w1h; wp.dl[4] = w1l;
        wp.src[5] = W2; wp.dh[5] = w2h; wp.dl[5] = w2l;
        wprep_all<<<4608, 256>>>(wp);
    }

    cudaMemcpyAsync(out, query, sizeof(float) * (size_t)Bn * NN * Dn,
                    cudaMemcpyDeviceToDevice);

    for (int l = 0; l < L_LAYERS; l++) {
        const int* il = inds + (size_t)l * ROWS;
        const size_t wd = (size_t)l * Dn * Dn;
        const size_t wf = (size_t)l * Dn * FFNn;

        gather_cls_kernel<<<ROWS, 256>>>(out, qpos, fgs, il, Wcls, bcls,
                                         tgt, tgh, tgl, qkh, qkl);

        {   // QKV batched -> head layouts
            GemmP p{};
            p.Ah[0] = qkh; p.Al[0] = qkl; p.Wh[0] = wqh + wd; p.Wl[0] = wql + wd;
            p.bias[0] = bq + l * Dn; p.Ch[0] = qh; p.Cl[0] = ql;
            p.Ah[1] = qkh; p.Al[1] = qkl; p.Wh[1] = wkh + wd; p.Wl[1] = wkl + wd;
            p.bias[1] = bk + l * Dn; p.Ch[1] = kh; p.Cl[1] = kl;
            p.Ah[2] = tgh; p.Al[2] = tgl; p.Wh[2] = wvh + wd; p.Wl[2] = wvl + wd;
            p.bias[2] = bv + l * Dn; p.Ch[2] = vh; p.Cl[2] = vl;
            gemm2<<<dim3(2, 64, 3), 128, G2_SMEM>>>(p, Dn, Dn, 3);
        }

        attn_tc<<<dim3(Bn * Hn, Kn / 128), 256, AT_SMEM>>>(qh, ql, kh, kl, vh, vl,
                                                           ath, atl);

        // O projection + LN1 fused (res = tgt) -> Xb, xh, xl
        gemm_ln<<<dim3(1, ROWS / 32), 256, GL_SMEM>>>(
            ath, atl, woh + wd, wol + wd,
            bo + l * Dn, g1 + l * Dn, be1 + l * Dn, tgt,
            Xb, xh, xl, nullptr, nullptr, nullptr, Dn, 1);

        {   // FFN1 (relu, bf16 split out)
            GemmP p{};
            p.Ah[0] = xh; p.Al[0] = xl; p.Wh[0] = w1h + wf; p.Wl[0] = w1l + wf;
            p.bias[0] = b1 + l * FFNn; p.Ch[0] = hh; p.Cl[0] = hl;
            gemm2<<<dim3(8, 64, 1), 128, G2_SMEM>>>(p, FFNn, Dn, 2);
        }

        // FFN2 + LN2 + ragged scatter fused (res = Xb) -> out
        gemm_ln<<<dim3(1, ROWS / 32), 256, GL_SMEM>>>(
            hh, hl, w2h + wf, w2l + wf,
            b2 + l * Dn, g2 + l * Dn, be2 + l * Dn, Xb,
            nullptr, nullptr, nullptr, out, il, fnum, FFNn, 2);
    }
}